// round 1
// baseline (speedup 1.0000x reference)
#include <cuda_runtime.h>
#include <cuda_bf16.h>
#include <math.h>

// ---------------- constants ----------------
#define BATCH 16
#define NF 64
#define LAT 512
#define IMGD 64
#define HW 4096          // 64*64
#define NC 4
#define CF 9
#define FIN 576          // NF*CF
#define FH 64
#define FO 64
#define NFREQ 6
#define FCH 24           // 4*NFREQ
#define CAT 2048         // LAT + NF*FCH
#define P_DYN 78016
// P layout offsets
#define OFF_KIN 0        // [64][576]
#define OFF_BIN 36864    // [64]
#define OFF_KOUT 36928   // [64][64]
#define OFF_BOUT 41024   // [64]
#define OFF_KSK 41088    // [64][576]
#define OFF_BSK 77952    // [64]

// ---------------- scratch (device globals; no allocation) ----------------
__device__ float g_chain[4 * BATCH * LAT];
__device__ float g_P[64ull * P_DYN];
__device__ float g_img0[BATCH * NF * HW];
__device__ float g_img1[BATCH * NF * HW];
__device__ float g_Z[(size_t)BATCH * FIN * HW];
__device__ float g_AT[BATCH * FIN * 128];
__device__ float g_bfold[BATCH * 128];
__device__ float g_mean[BATCH * FIN];
__device__ float g_rstd[BATCH * FIN];
__device__ float g_HS[(size_t)BATCH * 128 * HW];
__device__ float g_freq[BATCH * NF * FCH];
__device__ float g_latA[BATCH * LAT];
__device__ float g_latB[BATCH * LAT];
__device__ float g_t1[BATCH * CAT];

__device__ __forceinline__ float leaky(float v) { return v > 0.f ? v : 0.2f * v; }

// ---------------- input image projection ----------------
__global__ void k_inimg(const float* __restrict__ x, const float* __restrict__ w_in,
                        const float* __restrict__ b_in, float* __restrict__ img) {
    int idx = blockIdx.x * 256 + threadIdx.x;
    if (idx >= BATCH * NF * HW) return;
    int p = idx & (HW - 1);
    int o = (idx >> 12) & 63;
    int b = idx >> 18;
    const float* xb = x + (size_t)b * 3 * HW;
    float v = b_in[o] + w_in[o * 3 + 0] * xb[p] + w_in[o * 3 + 1] * xb[HW + p]
            + w_in[o * 3 + 2] * xb[2 * HW + p];
    img[idx] = v;
}

// ---------------- lin_res 512 (one block per batch row) ----------------
__global__ void k_linres512(const float* __restrict__ in, const float* __restrict__ w1,
                            const float* __restrict__ b1, const float* __restrict__ w2,
                            const float* __restrict__ b2, const float* __restrict__ ws,
                            const float* __restrict__ bs, float* __restrict__ out) {
    __shared__ float xr[LAT];
    __shared__ float hr[LAT];
    int b = blockIdx.x, j = threadIdx.x;
    xr[j] = in[b * LAT + j];
    __syncthreads();
    float a = b1[j];
#pragma unroll 4
    for (int k = 0; k < LAT; k++) a += xr[k] * w1[k * LAT + j];
    hr[j] = leaky(a);
    __syncthreads();
    float o = bs[j] + b2[j];
#pragma unroll 4
    for (int k = 0; k < LAT; k++) o += xr[k] * ws[k * LAT + j] + hr[k] * w2[k * LAT + j];
    out[b * LAT + j] = o;
}

// ---------------- dyn params GEMM: [64,512] @ [512,78016] + bias ----------------
__global__ __launch_bounds__(256) void k_dyngemm(const float* __restrict__ lat,
                                                 const float* __restrict__ W,
                                                 const float* __restrict__ bias,
                                                 float* __restrict__ P) {
    __shared__ float ls[32][65];
    int tid = threadIdx.y * 32 + threadIdx.x;
    int col0 = blockIdx.x * 128 + threadIdx.x * 4;
    bool ok = col0 < P_DYN;
    float acc[8][4];
#pragma unroll
    for (int r = 0; r < 8; r++)
#pragma unroll
        for (int c = 0; c < 4; c++) acc[r][c] = 0.f;

    for (int k0 = 0; k0 < LAT; k0 += 32) {
#pragma unroll
        for (int t = 0; t < 8; t++) {
            int idx = tid + t * 256;
            int m = idx >> 5, kk = idx & 31;
            ls[kk][m] = lat[m * LAT + k0 + kk];
        }
        __syncthreads();
        if (ok) {
#pragma unroll
            for (int kk = 0; kk < 32; kk++) {
                float4 w = *(const float4*)(W + (size_t)(k0 + kk) * P_DYN + col0);
#pragma unroll
                for (int r = 0; r < 8; r++) {
                    float l = ls[kk][threadIdx.y * 8 + r];
                    acc[r][0] += l * w.x; acc[r][1] += l * w.y;
                    acc[r][2] += l * w.z; acc[r][3] += l * w.w;
                }
            }
        }
        __syncthreads();
    }
    if (ok) {
        float4 bv = *(const float4*)(bias + col0);
#pragma unroll
        for (int r = 0; r < 8; r++) {
            int m = threadIdx.y * 8 + r;
            float4 o;
            o.x = acc[r][0] + bv.x; o.y = acc[r][1] + bv.y;
            o.z = acc[r][2] + bv.z; o.w = acc[r][3] + bv.w;
            *(float4*)(P + (size_t)m * P_DYN + col0) = o;
        }
    }
}

// ---------------- perceive + stats (Z materialize + mean/rstd) ----------------
__global__ void k_zstats(const float* __restrict__ img, float* __restrict__ Z,
                         float* __restrict__ mean, float* __restrict__ rstd) {
    int b = blockIdx.y;
    int i = blockIdx.x;                 // 0..575
    int g = i >> 6, f = i & 63;
    const float* O = img + (size_t)(b * NF + f) * HW;
    float* zrow = Z + ((size_t)b * FIN + i) * HW;
    double s1 = 0.0, s2 = 0.0;

    if (g == 0) {
        for (int p = threadIdx.x; p < HW; p += 256) {
            float v = O[p];
            zrow[p] = v; s1 += v; s2 += (double)v * v;
        }
    } else {
        int d = 1 << ((g - 1) >> 1);
        bool isSX = ((g - 1) & 1) == 0;
        for (int p = threadIdx.x; p < HW; p += 256) {
            int h = p >> 6, w = p & 63;
            int hm = h - d, hp = h + d, wm = w - d, wp = w + d;
            bool hmv = hm >= 0, hpv = hp < IMGD, wmv = wm >= 0, wpv = wp < IMGD;
            float v;
            if (isSX) {
                float t = 0.f;
                if (wmv) {
                    if (hmv) t -= O[hm * IMGD + wm];
                    t -= 2.f * O[h * IMGD + wm];
                    if (hpv) t -= O[hp * IMGD + wm];
                }
                if (wpv) {
                    if (hmv) t += O[hm * IMGD + wp];
                    t += 2.f * O[h * IMGD + wp];
                    if (hpv) t += O[hp * IMGD + wp];
                }
                v = 0.125f * t;
            } else {
                float t = 0.f;
                if (hmv) {
                    if (wmv) t -= O[hm * IMGD + wm];
                    t -= 2.f * O[hm * IMGD + w];
                    if (wpv) t -= O[hm * IMGD + wp];
                }
                if (hpv) {
                    if (wmv) t += O[hp * IMGD + wm];
                    t += 2.f * O[hp * IMGD + w];
                    if (wpv) t += O[hp * IMGD + wp];
                }
                v = 0.125f * t;
            }
            zrow[p] = v; s1 += v; s2 += (double)v * v;
        }
    }
    // block reduce (8 warps)
    __shared__ double rs1[8], rs2[8];
    int lane = threadIdx.x & 31, wid = threadIdx.x >> 5;
#pragma unroll
    for (int off = 16; off; off >>= 1) {
        s1 += __shfl_down_sync(0xffffffffu, s1, off);
        s2 += __shfl_down_sync(0xffffffffu, s2, off);
    }
    if (lane == 0) { rs1[wid] = s1; rs2[wid] = s2; }
    __syncthreads();
    if (threadIdx.x == 0) {
        double t1 = 0.0, t2 = 0.0;
        for (int w = 0; w < 8; w++) { t1 += rs1[w]; t2 += rs2[w]; }
        double m = t1 / 4096.0;
        double var = t2 / 4096.0 - m * m;
        mean[b * FIN + i] = (float)m;
        rstd[b * FIN + i] = 1.0f / sqrtf((float)var + 1e-5f);
    }
}

// ---------------- fold inorm into dynamic weights ----------------
__global__ void k_fold(const float* __restrict__ P, const float* __restrict__ mean,
                       const float* __restrict__ rstd, float* __restrict__ AT,
                       float* __restrict__ bfold) {
    int b = blockIdx.y, f = blockIdx.x;
    const float* pb = P + (size_t)b * P_DYN;
    int i = threadIdx.x;  // 0..575
    float r = rstd[b * FIN + i], m = mean[b * FIN + i];
    float win = pb[OFF_KIN + f * FIN + i] * r;
    float wsk = pb[OFF_KSK + f * FIN + i] * r;
    AT[(size_t)b * FIN * 128 + i * 128 + f] = win;
    AT[(size_t)b * FIN * 128 + i * 128 + 64 + f] = wsk;
    float t1 = win * m, t2 = wsk * m;
    // reduce over 576 threads = 18 warps
    __shared__ float r1[18], r2[18];
    int lane = threadIdx.x & 31, wid = threadIdx.x >> 5;
#pragma unroll
    for (int off = 16; off; off >>= 1) {
        t1 += __shfl_down_sync(0xffffffffu, t1, off);
        t2 += __shfl_down_sync(0xffffffffu, t2, off);
    }
    if (lane == 0) { r1[wid] = t1; r2[wid] = t2; }
    __syncthreads();
    if (threadIdx.x == 0) {
        float s1 = 0.f, s2 = 0.f;
        for (int w = 0; w < 18; w++) { s1 += r1[w]; s2 += r2[w]; }
        bfold[b * 128 + f] = pb[OFF_BIN + f] - s1;
        bfold[b * 128 + 64 + f] = pb[OFF_BSK + f] - s2;
    }
}

// ---------------- main GEMM: [128,576]@[576,4096] per batch ----------------
__global__ __launch_bounds__(256) void k_g1(const float* __restrict__ AT,
                                            const float* __restrict__ Z,
                                            const float* __restrict__ bfold,
                                            float* __restrict__ HS) {
    __shared__ float As[8][132];
    __shared__ float Bs[8][132];
    int b = blockIdx.y;
    int p0 = blockIdx.x * 128;
    const float* At = AT + (size_t)b * FIN * 128;
    const float* Zb = Z + (size_t)b * FIN * HW;
    int tid = threadIdx.x;
    int tx = tid & 15, ty = tid >> 4;

    float acc[8][8];
#pragma unroll
    for (int r = 0; r < 8; r++)
#pragma unroll
        for (int c = 0; c < 8; c++) acc[r][c] = 0.f;

    int lkk = tid >> 5;          // warp id = k row loaded
    int lcol = (tid & 31) * 4;   // 4 floats per thread
    for (int k0 = 0; k0 < FIN; k0 += 8) {
        float4 va = *(const float4*)(At + (size_t)(k0 + lkk) * 128 + lcol);
        float4 vb = *(const float4*)(Zb + (size_t)(k0 + lkk) * HW + p0 + lcol);
        *(float4*)&As[lkk][lcol] = va;
        *(float4*)&Bs[lkk][lcol] = vb;
        __syncthreads();
#pragma unroll
        for (int kk = 0; kk < 8; kk++) {
            float a[8], bb[8];
#pragma unroll
            for (int r = 0; r < 8; r++) a[r] = As[kk][ty * 8 + r];
#pragma unroll
            for (int c = 0; c < 8; c++) bb[c] = Bs[kk][tx * 8 + c];
#pragma unroll
            for (int r = 0; r < 8; r++)
#pragma unroll
                for (int c = 0; c < 8; c++) acc[r][c] += a[r] * bb[c];
        }
        __syncthreads();
    }
#pragma unroll
    for (int r = 0; r < 8; r++) {
        int row = ty * 8 + r;
        float bias = bfold[b * 128 + row];
        float* dst = HS + ((size_t)b * 128 + row) * HW + p0 + tx * 8;
#pragma unroll
        for (int c = 0; c < 8; c++) {
            float v = acc[r][c] + bias;
            if (row < 64) v = leaky(v);
            dst[c] = v;
        }
    }
}

// ---------------- second GEMM + skip: out = k_out@H + b_out + S ----------------
__global__ __launch_bounds__(256) void k_g2(const float* __restrict__ P,
                                            const float* __restrict__ HS,
                                            float* __restrict__ outimg) {
    __shared__ float ko[64][65];
    int b = blockIdx.y;
    const float* pb = P + (size_t)b * P_DYN;
    int tid = threadIdx.y * 32 + threadIdx.x;
    for (int idx = tid; idx < 4096; idx += 256) ko[idx >> 6][idx & 63] = pb[OFF_KOUT + idx];
    __syncthreads();

    int col0 = blockIdx.x * 128 + threadIdx.x * 4;
    int r0 = threadIdx.y * 8;
    const float* Hb = HS + (size_t)b * 128 * HW;
    float acc[8][4];
#pragma unroll
    for (int r = 0; r < 8; r++)
#pragma unroll
        for (int c = 0; c < 4; c++) acc[r][c] = 0.f;

#pragma unroll 4
    for (int f = 0; f < 64; f++) {
        float4 h = *(const float4*)(Hb + (size_t)f * HW + col0);
#pragma unroll
        for (int r = 0; r < 8; r++) {
            float w = ko[r0 + r][f];
            acc[r][0] += w * h.x; acc[r][1] += w * h.y;
            acc[r][2] += w * h.z; acc[r][3] += w * h.w;
        }
    }
#pragma unroll
    for (int r = 0; r < 8; r++) {
        int o = r0 + r;
        float bo = pb[OFF_BOUT + o];
        float4 s = *(const float4*)(Hb + (size_t)(64 + o) * HW + col0);
        float4 v;
        v.x = acc[r][0] + bo + s.x; v.y = acc[r][1] + bo + s.y;
        v.z = acc[r][2] + bo + s.z; v.w = acc[r][3] + bo + s.w;
        *(float4*)(outimg + ((size_t)b * NF + o) * HW + col0) = v;
    }
}

// ---------------- frequency readout ----------------
__global__ void k_freq(const float* __restrict__ img, const float* __restrict__ pe,
                       float* __restrict__ freqout) {
    int b = blockIdx.y, ch = blockIdx.x;
    const float* O = img + (size_t)(b * NF + ch) * HW;
    float acc[FCH];
#pragma unroll
    for (int f = 0; f < FCH; f++) acc[f] = 0.f;
    for (int p = threadIdx.x; p < HW; p += 256) {
        float v = O[p];
#pragma unroll
        for (int f = 0; f < FCH; f++) acc[f] += v * pe[f * HW + p];
    }
    __shared__ float red[FCH][9];
    int lane = threadIdx.x & 31, wid = threadIdx.x >> 5;
#pragma unroll
    for (int f = 0; f < FCH; f++) {
        float v = acc[f];
#pragma unroll
        for (int off = 16; off; off >>= 1) v += __shfl_down_sync(0xffffffffu, v, off);
        if (lane == 0) red[f][wid] = v;
    }
    __syncthreads();
    if (threadIdx.x < FCH) {
        float s = 0.f;
        for (int w = 0; w < 8; w++) s += red[threadIdx.x][w];
        freqout[b * (NF * FCH) + ch * FCH + threadIdx.x] = s * (1.0f / 4096.0f);
    }
}

// ---------------- otl phase A: t1 = leaky(cat @ w1 + b1) ----------------
__global__ void k_otlA(const float* __restrict__ lat, const float* __restrict__ freq,
                       const float* __restrict__ w1, const float* __restrict__ b1,
                       float* __restrict__ t1) {
    __shared__ float cat[CAT];
    int b = blockIdx.x;
    int j = blockIdx.y * 128 + threadIdx.x;
    for (int t = threadIdx.x; t < CAT; t += 128)
        cat[t] = (t < LAT) ? lat[b * LAT + t] : freq[b * (CAT - LAT) + t - LAT];
    __syncthreads();
    float a = b1[j];
#pragma unroll 4
    for (int k = 0; k < CAT; k++) a += cat[k] * w1[(size_t)k * CAT + j];
    t1[b * CAT + j] = leaky(a);
}

// ---------------- otl phase B: lat' = cat@ws + bs + t1@w2 + b2 ----------------
__global__ void k_otlB(const float* __restrict__ lat, const float* __restrict__ freq,
                       const float* __restrict__ t1, const float* __restrict__ w2,
                       const float* __restrict__ b2, const float* __restrict__ ws,
                       const float* __restrict__ bs, float* __restrict__ latout) {
    __shared__ float cat[CAT];
    __shared__ float t1s[CAT];
    int b = blockIdx.x;
    int j = blockIdx.y * 128 + threadIdx.x;
    for (int t = threadIdx.x; t < CAT; t += 128) {
        cat[t] = (t < LAT) ? lat[b * LAT + t] : freq[b * (CAT - LAT) + t - LAT];
        t1s[t] = t1[b * CAT + t];
    }
    __syncthreads();
    float o = bs[j] + b2[j];
#pragma unroll 4
    for (int k = 0; k < CAT; k++)
        o += cat[k] * ws[(size_t)k * LAT + j] + t1s[k] * w2[(size_t)k * LAT + j];
    latout[b * LAT + j] = o;
}

// ---------------- final projection ----------------
__global__ void k_final(const float* __restrict__ lat, const float* __restrict__ w,
                        const float* __restrict__ bb, float* __restrict__ out) {
    __shared__ float xr[LAT];
    int b = blockIdx.x, j = threadIdx.x;
    xr[j] = lat[b * LAT + j];
    __syncthreads();
    float o = bb[j];
#pragma unroll 4
    for (int k = 0; k < LAT; k++) o += xr[k] * w[k * LAT + j];
    out[b * LAT + j] = o;
}

// ---------------- launch ----------------
extern "C" void kernel_launch(void* const* d_in, const int* in_sizes, int n_in,
                              void* d_out, int out_size) {
    const float* x       = (const float*)d_in[0];
    const float* inj_lat = (const float*)d_in[1];
    const float* w_in    = (const float*)d_in[2];
    const float* b_in    = (const float*)d_in[3];
    const float* fl_w1   = (const float*)d_in[4];
    const float* fl_b1   = (const float*)d_in[5];
    const float* fl_w2   = (const float*)d_in[6];
    const float* fl_b2   = (const float*)d_in[7];
    const float* fl_ws   = (const float*)d_in[8];
    const float* fl_bs   = (const float*)d_in[9];
    const float* dyn_w   = (const float*)d_in[10];
    const float* dyn_b   = (const float*)d_in[11];
    const float* pe      = (const float*)d_in[12];
    const float* otl_w1  = (const float*)d_in[13];
    const float* otl_b1  = (const float*)d_in[14];
    const float* otl_w2  = (const float*)d_in[15];
    const float* otl_b2  = (const float*)d_in[16];
    const float* otl_ws  = (const float*)d_in[17];
    const float* otl_bs  = (const float*)d_in[18];
    const float* ltl_w   = (const float*)d_in[19];
    const float* ltl_b   = (const float*)d_in[20];

    float *chain, *P, *img0, *img1, *Z, *AT, *bfold, *meanb, *rstdb, *HS, *freqb, *latA, *latB, *t1b;
    cudaGetSymbolAddress((void**)&chain, g_chain);
    cudaGetSymbolAddress((void**)&P, g_P);
    cudaGetSymbolAddress((void**)&img0, g_img0);
    cudaGetSymbolAddress((void**)&img1, g_img1);
    cudaGetSymbolAddress((void**)&Z, g_Z);
    cudaGetSymbolAddress((void**)&AT, g_AT);
    cudaGetSymbolAddress((void**)&bfold, g_bfold);
    cudaGetSymbolAddress((void**)&meanb, g_mean);
    cudaGetSymbolAddress((void**)&rstdb, g_rstd);
    cudaGetSymbolAddress((void**)&HS, g_HS);
    cudaGetSymbolAddress((void**)&freqb, g_freq);
    cudaGetSymbolAddress((void**)&latA, g_latA);
    cudaGetSymbolAddress((void**)&latB, g_latB);
    cudaGetSymbolAddress((void**)&t1b, g_t1);

    cudaMemsetAsync(latA, 0, BATCH * LAT * sizeof(float));

    k_inimg<<<(BATCH * NF * HW + 255) / 256, 256>>>(x, w_in, b_in, img0);

    // latent chain (image-independent) hoisted up front
    k_linres512<<<BATCH, LAT>>>(inj_lat, fl_w1, fl_b1, fl_w2, fl_b2, fl_ws, fl_bs, chain);
    for (int t = 1; t < 4; t++)
        k_linres512<<<BATCH, LAT>>>(chain + (t - 1) * BATCH * LAT, fl_w1, fl_b1, fl_w2,
                                    fl_b2, fl_ws, fl_bs, chain + t * BATCH * LAT);

    // all 4 iterations' dynamic params in ONE pass over dyn_w
    k_dyngemm<<<(P_DYN + 127) / 128, dim3(32, 8)>>>(chain, dyn_w, dyn_b, P);

    float* cur = img0; float* nxt = img1;
    float* lcur = latA; float* lnxt = latB;
    for (int c = 0; c < NC; c++) {
        const float* Pc = P + (size_t)c * BATCH * P_DYN;
        k_zstats<<<dim3(FIN, BATCH), 256>>>(cur, Z, meanb, rstdb);
        k_fold<<<dim3(64, BATCH), FIN>>>(Pc, meanb, rstdb, AT, bfold);
        k_g1<<<dim3(HW / 128, BATCH), 256>>>(AT, Z, bfold, HS);
        k_g2<<<dim3(HW / 128, BATCH), dim3(32, 8)>>>(Pc, HS, nxt);
        k_freq<<<dim3(NF, BATCH), 256>>>(nxt, pe, freqb);
        k_otlA<<<dim3(BATCH, CAT / 128), 128>>>(lcur, freqb, otl_w1 + (size_t)c * CAT * CAT,
                                                otl_b1 + c * CAT, t1b);
        k_otlB<<<dim3(BATCH, LAT / 128), 128>>>(lcur, freqb, t1b,
                                                otl_w2 + (size_t)c * CAT * LAT, otl_b2 + c * LAT,
                                                otl_ws + (size_t)c * CAT * LAT, otl_bs + c * LAT,
                                                lnxt);
        { float* t = cur; cur = nxt; nxt = t; }
        { float* t = lcur; lcur = lnxt; lnxt = t; }
    }
    k_final<<<BATCH, LAT>>>(lcur, ltl_w, ltl_b, (float*)d_out);
}

// round 3
// speedup vs baseline: 1.2203x; 1.2203x over previous
#include <cuda_runtime.h>
#include <cuda_bf16.h>
#include <math.h>

// ---------------- constants ----------------
#define BATCH 16
#define NF 64
#define LAT 512
#define IMGD 64
#define HW 4096          // 64*64
#define NC 4
#define CF 9
#define FIN 576          // NF*CF
#define NFREQ 6
#define FCH 24           // 4*NFREQ
#define FREQN 1536       // NF*FCH
#define CAT 2048         // LAT + NF*FCH
#define P_DYN 78016
// P layout offsets
#define OFF_KIN 0        // [64][576]
#define OFF_BIN 36864    // [64]
#define OFF_KOUT 36928   // [64][64]
#define OFF_BOUT 41024   // [64]
#define OFF_KSK 41088    // [64][576]
#define OFF_BSK 77952    // [64]

// ---------------- scratch (device globals; no allocation) ----------------
__device__ float g_chain[4 * BATCH * LAT];
__device__ float g_hbuf[BATCH * LAT];
__device__ float g_P[64ull * P_DYN];
__device__ float g_img0[BATCH * NF * HW];
__device__ float g_img1[BATCH * NF * HW];
__device__ float g_Z[(size_t)BATCH * FIN * HW];
__device__ float g_AT[BATCH * FIN * 128];
__device__ float g_bfold[BATCH * 128];
__device__ float g_mean[BATCH * FIN];
__device__ float g_rstd[BATCH * FIN];
__device__ float g_HS[(size_t)BATCH * 128 * HW];
__device__ float g_freq[BATCH * FREQN];
__device__ float g_latA[BATCH * LAT];
__device__ float g_latB[BATCH * LAT];
__device__ float g_t1[BATCH * CAT];

__device__ __forceinline__ float leaky(float v) { return v > 0.f ? v : 0.2f * v; }

__device__ __forceinline__ unsigned f2tf(float v) {
    unsigned r;
    asm("cvt.rna.tf32.f32 %0, %1;" : "=r"(r) : "f"(v));
    return r;
}

// ---------------- input image projection ----------------
__global__ void k_inimg(const float* __restrict__ x, const float* __restrict__ w_in,
                        const float* __restrict__ b_in, float* __restrict__ img) {
    int idx = blockIdx.x * 256 + threadIdx.x;
    if (idx >= BATCH * NF * HW) return;
    int p = idx & (HW - 1);
    int o = (idx >> 12) & 63;
    int b = idx >> 18;
    const float* xb = x + (size_t)b * 3 * HW;
    float v = b_in[o] + w_in[o * 3 + 0] * xb[p] + w_in[o * 3 + 1] * xb[HW + p]
            + w_in[o * 3 + 2] * xb[2 * HW + p];
    img[idx] = v;
}

// ---------------- lin_res 512: phase 1 (h = leaky(x@w1 + b1)) ----------------
// grid (4 jblocks, 4 batchgroups), block 128
__global__ __launch_bounds__(128) void k_lin_h(const float* __restrict__ in,
                                               const float* __restrict__ w1,
                                               const float* __restrict__ b1,
                                               float* __restrict__ H) {
    __shared__ float xs[4][LAT];
    int j = blockIdx.x * 128 + threadIdx.x;
    int bb0 = blockIdx.y * 4;
    for (int t = threadIdx.x; t < 4 * LAT; t += 128)
        xs[t >> 9][t & 511] = in[(bb0 + (t >> 9)) * LAT + (t & 511)];
    __syncthreads();
    float acc0 = 0.f, acc1 = 0.f, acc2 = 0.f, acc3 = 0.f;
#pragma unroll 8
    for (int k = 0; k < LAT; k++) {
        float w = w1[(size_t)k * LAT + j];
        acc0 += xs[0][k] * w; acc1 += xs[1][k] * w;
        acc2 += xs[2][k] * w; acc3 += xs[3][k] * w;
    }
    float bb = b1[j];
    H[(bb0 + 0) * LAT + j] = leaky(acc0 + bb);
    H[(bb0 + 1) * LAT + j] = leaky(acc1 + bb);
    H[(bb0 + 2) * LAT + j] = leaky(acc2 + bb);
    H[(bb0 + 3) * LAT + j] = leaky(acc3 + bb);
}

// ---------------- lin_res 512: phase 2 (o = x@ws + h@w2 + bs + b2) ----------------
__global__ __launch_bounds__(128) void k_lin_o(const float* __restrict__ in,
                                               const float* __restrict__ H,
                                               const float* __restrict__ ws,
                                               const float* __restrict__ w2,
                                               const float* __restrict__ bs,
                                               const float* __restrict__ b2,
                                               float* __restrict__ out) {
    __shared__ float xs[4][LAT];
    __shared__ float hs[4][LAT];
    int j = blockIdx.x * 128 + threadIdx.x;
    int bb0 = blockIdx.y * 4;
    for (int t = threadIdx.x; t < 4 * LAT; t += 128) {
        xs[t >> 9][t & 511] = in[(bb0 + (t >> 9)) * LAT + (t & 511)];
        hs[t >> 9][t & 511] = H[(bb0 + (t >> 9)) * LAT + (t & 511)];
    }
    __syncthreads();
    float acc0 = 0.f, acc1 = 0.f, acc2 = 0.f, acc3 = 0.f;
#pragma unroll 4
    for (int k = 0; k < LAT; k++) {
        float a = ws[(size_t)k * LAT + j];
        float c = w2[(size_t)k * LAT + j];
        acc0 += xs[0][k] * a + hs[0][k] * c;
        acc1 += xs[1][k] * a + hs[1][k] * c;
        acc2 += xs[2][k] * a + hs[2][k] * c;
        acc3 += xs[3][k] * a + hs[3][k] * c;
    }
    float bb = bs[j] + b2[j];
    out[(bb0 + 0) * LAT + j] = acc0 + bb;
    out[(bb0 + 1) * LAT + j] = acc1 + bb;
    out[(bb0 + 2) * LAT + j] = acc2 + bb;
    out[(bb0 + 3) * LAT + j] = acc3 + bb;
}

// ---------------- dyn params GEMM: [64,512] @ [512,78016] + bias ----------------
__global__ __launch_bounds__(256) void k_dyngemm(const float* __restrict__ lat,
                                                 const float* __restrict__ W,
                                                 const float* __restrict__ bias,
                                                 float* __restrict__ P) {
    __shared__ float ls[32][65];
    int tid = threadIdx.y * 32 + threadIdx.x;
    int col0 = blockIdx.x * 128 + threadIdx.x * 4;
    bool ok = col0 < P_DYN;
    float acc[8][4];
#pragma unroll
    for (int r = 0; r < 8; r++)
#pragma unroll
        for (int c = 0; c < 4; c++) acc[r][c] = 0.f;

    for (int k0 = 0; k0 < LAT; k0 += 32) {
#pragma unroll
        for (int t = 0; t < 8; t++) {
            int idx = tid + t * 256;
            int m = idx >> 5, kk = idx & 31;
            ls[kk][m] = lat[m * LAT + k0 + kk];
        }
        __syncthreads();
        if (ok) {
#pragma unroll
            for (int kk = 0; kk < 32; kk++) {
                float4 w = *(const float4*)(W + (size_t)(k0 + kk) * P_DYN + col0);
#pragma unroll
                for (int r = 0; r < 8; r++) {
                    float l = ls[kk][threadIdx.y * 8 + r];
                    acc[r][0] += l * w.x; acc[r][1] += l * w.y;
                    acc[r][2] += l * w.z; acc[r][3] += l * w.w;
                }
            }
        }
        __syncthreads();
    }
    if (ok) {
        float4 bv = *(const float4*)(bias + col0);
#pragma unroll
        for (int r = 0; r < 8; r++) {
            int m = threadIdx.y * 8 + r;
            float4 o;
            o.x = acc[r][0] + bv.x; o.y = acc[r][1] + bv.y;
            o.z = acc[r][2] + bv.z; o.w = acc[r][3] + bv.w;
            *(float4*)(P + (size_t)m * P_DYN + col0) = o;
        }
    }
}

// ---------------- perceive + stats (Z materialize + mean/rstd) ----------------
__global__ void k_zstats(const float* __restrict__ img, float* __restrict__ Z,
                         float* __restrict__ mean, float* __restrict__ rstd) {
    int b = blockIdx.y;
    int i = blockIdx.x;                 // 0..575
    int g = i >> 6, f = i & 63;
    const float* O = img + (size_t)(b * NF + f) * HW;
    float* zrow = Z + ((size_t)b * FIN + i) * HW;
    double s1 = 0.0, s2 = 0.0;

    if (g == 0) {
        for (int p = threadIdx.x; p < HW; p += 256) {
            float v = O[p];
            zrow[p] = v; s1 += v; s2 += (double)v * v;
        }
    } else {
        int d = 1 << ((g - 1) >> 1);
        bool isSX = ((g - 1) & 1) == 0;
        for (int p = threadIdx.x; p < HW; p += 256) {
            int h = p >> 6, w = p & 63;
            int hm = h - d, hp = h + d, wm = w - d, wp = w + d;
            bool hmv = hm >= 0, hpv = hp < IMGD, wmv = wm >= 0, wpv = wp < IMGD;
            float v;
            if (isSX) {
                float t = 0.f;
                if (wmv) {
                    if (hmv) t -= O[hm * IMGD + wm];
                    t -= 2.f * O[h * IMGD + wm];
                    if (hpv) t -= O[hp * IMGD + wm];
                }
                if (wpv) {
                    if (hmv) t += O[hm * IMGD + wp];
                    t += 2.f * O[h * IMGD + wp];
                    if (hpv) t += O[hp * IMGD + wp];
                }
                v = 0.125f * t;
            } else {
                float t = 0.f;
                if (hmv) {
                    if (wmv) t -= O[hm * IMGD + wm];
                    t -= 2.f * O[hm * IMGD + w];
                    if (wpv) t -= O[hm * IMGD + wp];
                }
                if (hpv) {
                    if (wmv) t += O[hp * IMGD + wm];
                    t += 2.f * O[hp * IMGD + w];
                    if (wpv) t += O[hp * IMGD + wp];
                }
                v = 0.125f * t;
            }
            zrow[p] = v; s1 += v; s2 += (double)v * v;
        }
    }
    __shared__ double rs1[8], rs2[8];
    int lane = threadIdx.x & 31, wid = threadIdx.x >> 5;
#pragma unroll
    for (int off = 16; off; off >>= 1) {
        s1 += __shfl_down_sync(0xffffffffu, s1, off);
        s2 += __shfl_down_sync(0xffffffffu, s2, off);
    }
    if (lane == 0) { rs1[wid] = s1; rs2[wid] = s2; }
    __syncthreads();
    if (threadIdx.x == 0) {
        double t1 = 0.0, t2 = 0.0;
        for (int w = 0; w < 8; w++) { t1 += rs1[w]; t2 += rs2[w]; }
        double m = t1 / 4096.0;
        double var = t2 / 4096.0 - m * m;
        mean[b * FIN + i] = (float)m;
        rstd[b * FIN + i] = 1.0f / sqrtf((float)var + 1e-5f);
    }
}

// ---------------- fold inorm into dynamic weights ----------------
__global__ void k_fold(const float* __restrict__ P, const float* __restrict__ mean,
                       const float* __restrict__ rstd, float* __restrict__ AT,
                       float* __restrict__ bfold) {
    int b = blockIdx.y, f = blockIdx.x;
    const float* pb = P + (size_t)b * P_DYN;
    int i = threadIdx.x;  // 0..575
    float r = rstd[b * FIN + i], m = mean[b * FIN + i];
    float win = pb[OFF_KIN + f * FIN + i] * r;
    float wsk = pb[OFF_KSK + f * FIN + i] * r;
    AT[(size_t)b * FIN * 128 + i * 128 + f] = win;
    AT[(size_t)b * FIN * 128 + i * 128 + 64 + f] = wsk;
    float t1 = win * m, t2 = wsk * m;
    __shared__ float r1[18], r2[18];
    int lane = threadIdx.x & 31, wid = threadIdx.x >> 5;
#pragma unroll
    for (int off = 16; off; off >>= 1) {
        t1 += __shfl_down_sync(0xffffffffu, t1, off);
        t2 += __shfl_down_sync(0xffffffffu, t2, off);
    }
    if (lane == 0) { r1[wid] = t1; r2[wid] = t2; }
    __syncthreads();
    if (threadIdx.x == 0) {
        float s1 = 0.f, s2 = 0.f;
        for (int w = 0; w < 18; w++) { s1 += r1[w]; s2 += r2[w]; }
        bfold[b * 128 + f] = pb[OFF_BIN + f] - s1;
        bfold[b * 128 + 64 + f] = pb[OFF_BSK + f] - s2;
    }
}

// ---------------- main GEMM via tf32 mma.sync: [128,576]@[576,4096] per batch ----------------
// grid (32 px-tiles, 16 batch), block 256 (8 warps: 2 m-halves x 4 n-quarters)
__global__ __launch_bounds__(256) void k_g1_mma(const float* __restrict__ AT,
                                                const float* __restrict__ Z,
                                                const float* __restrict__ bfold,
                                                float* __restrict__ HS) {
    __shared__ unsigned As[2][16][136];
    __shared__ unsigned Bs[2][16][136];
    int b = blockIdx.y;
    int p0 = blockIdx.x * 128;
    const float* At = AT + (size_t)b * FIN * 128;
    const float* Zb = Z + (size_t)b * FIN * HW;
    int tid = threadIdx.x, lane = tid & 31, warp = tid >> 5;
    int ch0 = (warp & 1) * 64;
    int px0 = (warp >> 1) * 32;
    int r = lane >> 2, cc = lane & 3;

    float acc[4][4][4];
#pragma unroll
    for (int mt = 0; mt < 4; mt++)
#pragma unroll
        for (int nt = 0; nt < 4; nt++)
#pragma unroll
            for (int q = 0; q < 4; q++) acc[mt][nt][q] = 0.f;

    int rowL = tid >> 5;        // 0..7
    int colL = lane * 4;        // 0..124

    // stage chunk 0
    float4 va0 = *(const float4*)(At + (size_t)rowL * 128 + colL);
    float4 va1 = *(const float4*)(At + (size_t)(rowL + 8) * 128 + colL);
    float4 vb0 = *(const float4*)(Zb + (size_t)rowL * HW + p0 + colL);
    float4 vb1 = *(const float4*)(Zb + (size_t)(rowL + 8) * HW + p0 + colL);
    *(uint4*)&As[0][rowL][colL]     = make_uint4(f2tf(va0.x), f2tf(va0.y), f2tf(va0.z), f2tf(va0.w));
    *(uint4*)&As[0][rowL + 8][colL] = make_uint4(f2tf(va1.x), f2tf(va1.y), f2tf(va1.z), f2tf(va1.w));
    *(uint4*)&Bs[0][rowL][colL]     = make_uint4(f2tf(vb0.x), f2tf(vb0.y), f2tf(vb0.z), f2tf(vb0.w));
    *(uint4*)&Bs[0][rowL + 8][colL] = make_uint4(f2tf(vb1.x), f2tf(vb1.y), f2tf(vb1.z), f2tf(vb1.w));
    __syncthreads();

    for (int t = 0; t < 36; t++) {
        int cur = t & 1;
        float4 na0, na1, nb0, nb1;
        if (t < 35) {
            int i0 = (t + 1) * 16;
            na0 = *(const float4*)(At + (size_t)(i0 + rowL) * 128 + colL);
            na1 = *(const float4*)(At + (size_t)(i0 + rowL + 8) * 128 + colL);
            nb0 = *(const float4*)(Zb + (size_t)(i0 + rowL) * HW + p0 + colL);
            nb1 = *(const float4*)(Zb + (size_t)(i0 + rowL + 8) * HW + p0 + colL);
        }
#pragma unroll
        for (int ks = 0; ks < 2; ks++) {
            int kk = ks * 8;
            unsigned af[4][4], bf[4][2];
#pragma unroll
            for (int mt = 0; mt < 4; mt++) {
                int m = ch0 + mt * 16;
                af[mt][0] = As[cur][kk + cc][m + r];
                af[mt][1] = As[cur][kk + cc][m + r + 8];
                af[mt][2] = As[cur][kk + cc + 4][m + r];
                af[mt][3] = As[cur][kk + cc + 4][m + r + 8];
            }
#pragma unroll
            for (int nt = 0; nt < 4; nt++) {
                int n = px0 + nt * 8 + r;
                bf[nt][0] = Bs[cur][kk + cc][n];
                bf[nt][1] = Bs[cur][kk + cc + 4][n];
            }
#pragma unroll
            for (int mt = 0; mt < 4; mt++)
#pragma unroll
                for (int nt = 0; nt < 4; nt++) {
                    asm volatile(
                        "mma.sync.aligned.m16n8k8.row.col.f32.tf32.tf32.f32 "
                        "{%0,%1,%2,%3}, {%4,%5,%6,%7}, {%8,%9}, {%0,%1,%2,%3};"
                        : "+f"(acc[mt][nt][0]), "+f"(acc[mt][nt][1]),
                          "+f"(acc[mt][nt][2]), "+f"(acc[mt][nt][3])
                        : "r"(af[mt][0]), "r"(af[mt][1]), "r"(af[mt][2]), "r"(af[mt][3]),
                          "r"(bf[nt][0]), "r"(bf[nt][1]));
                }
        }
        if (t < 35) {
            int nxt = cur ^ 1;
            *(uint4*)&As[nxt][rowL][colL]     = make_uint4(f2tf(na0.x), f2tf(na0.y), f2tf(na0.z), f2tf(na0.w));
            *(uint4*)&As[nxt][rowL + 8][colL] = make_uint4(f2tf(na1.x), f2tf(na1.y), f2tf(na1.z), f2tf(na1.w));
            *(uint4*)&Bs[nxt][rowL][colL]     = make_uint4(f2tf(nb0.x), f2tf(nb0.y), f2tf(nb0.z), f2tf(nb0.w));
            *(uint4*)&Bs[nxt][rowL + 8][colL] = make_uint4(f2tf(nb1.x), f2tf(nb1.y), f2tf(nb1.z), f2tf(nb1.w));
        }
        __syncthreads();
    }

    // epilogue: bias + leaky(rows<64) + store
#pragma unroll
    for (int mt = 0; mt < 4; mt++) {
        int row0 = ch0 + mt * 16 + r;
        int row1 = row0 + 8;
        float bi0 = bfold[b * 128 + row0];
        float bi1 = bfold[b * 128 + row1];
        bool lk = (ch0 == 0);
#pragma unroll
        for (int nt = 0; nt < 4; nt++) {
            int gcol = p0 + px0 + nt * 8 + 2 * cc;
            float v0 = acc[mt][nt][0] + bi0, v1 = acc[mt][nt][1] + bi0;
            float v2 = acc[mt][nt][2] + bi1, v3 = acc[mt][nt][3] + bi1;
            if (lk) { v0 = leaky(v0); v1 = leaky(v1); v2 = leaky(v2); v3 = leaky(v3); }
            *(float2*)(HS + ((size_t)b * 128 + row0) * HW + gcol) = make_float2(v0, v1);
            *(float2*)(HS + ((size_t)b * 128 + row1) * HW + gcol) = make_float2(v2, v3);
        }
    }
}

// ---------------- second GEMM + skip: out = k_out@H + b_out + S ----------------
__global__ __launch_bounds__(256) void k_g2(const float* __restrict__ P,
                                            const float* __restrict__ HS,
                                            float* __restrict__ outimg) {
    __shared__ float ko[64][65];
    int b = blockIdx.y;
    const float* pb = P + (size_t)b * P_DYN;
    int tid = threadIdx.y * 32 + threadIdx.x;
    for (int idx = tid; idx < 4096; idx += 256) ko[idx >> 6][idx & 63] = pb[OFF_KOUT + idx];
    __syncthreads();

    int col0 = blockIdx.x * 128 + threadIdx.x * 4;
    int r0 = threadIdx.y * 8;
    const float* Hb = HS + (size_t)b * 128 * HW;
    float acc[8][4];
#pragma unroll
    for (int r = 0; r < 8; r++)
#pragma unroll
        for (int c = 0; c < 4; c++) acc[r][c] = 0.f;

#pragma unroll 4
    for (int f = 0; f < 64; f++) {
        float4 h = *(const float4*)(Hb + (size_t)f * HW + col0);
#pragma unroll
        for (int r = 0; r < 8; r++) {
            float w = ko[r0 + r][f];
            acc[r][0] += w * h.x; acc[r][1] += w * h.y;
            acc[r][2] += w * h.z; acc[r][3] += w * h.w;
        }
    }
#pragma unroll
    for (int r = 0; r < 8; r++) {
        int o = r0 + r;
        float bo = pb[OFF_BOUT + o];
        float4 s = *(const float4*)(Hb + (size_t)(64 + o) * HW + col0);
        float4 v;
        v.x = acc[r][0] + bo + s.x; v.y = acc[r][1] + bo + s.y;
        v.z = acc[r][2] + bo + s.z; v.w = acc[r][3] + bo + s.w;
        *(float4*)(outimg + ((size_t)b * NF + o) * HW + col0) = v;
    }
}

// ---------------- frequency readout ----------------
__global__ void k_freq(const float* __restrict__ img, const float* __restrict__ pe,
                       float* __restrict__ freqout) {
    int b = blockIdx.y, ch = blockIdx.x;
    const float* O = img + (size_t)(b * NF + ch) * HW;
    float acc[FCH];
#pragma unroll
    for (int f = 0; f < FCH; f++) acc[f] = 0.f;
    for (int p = threadIdx.x; p < HW; p += 256) {
        float v = O[p];
#pragma unroll
        for (int f = 0; f < FCH; f++) acc[f] += v * pe[f * HW + p];
    }
    __shared__ float red[FCH][9];
    int lane = threadIdx.x & 31, wid = threadIdx.x >> 5;
#pragma unroll
    for (int f = 0; f < FCH; f++) {
        float v = acc[f];
#pragma unroll
        for (int off = 16; off; off >>= 1) v += __shfl_down_sync(0xffffffffu, v, off);
        if (lane == 0) red[f][wid] = v;
    }
    __syncthreads();
    if (threadIdx.x < FCH) {
        float s = 0.f;
        for (int w = 0; w < 8; w++) s += red[threadIdx.x][w];
        freqout[b * FREQN + ch * FCH + threadIdx.x] = s * (1.0f / 4096.0f);
    }
}

// ---------------- otl phase A: t1 = leaky(cat @ w1 + b1) ----------------
// grid (16 jblocks, 4 batchgroups), block 128
__global__ __launch_bounds__(128) void k_cat_h(const float* __restrict__ lat,
                                               const float* __restrict__ freq,
                                               const float* __restrict__ w1,
                                               const float* __restrict__ b1,
                                               float* __restrict__ t1) {
    __shared__ float cs[4][CAT];
    int j = blockIdx.x * 128 + threadIdx.x;
    int bb0 = blockIdx.y * 4;
    for (int t = threadIdx.x; t < 4 * CAT; t += 128) {
        int bb = t >> 11, k = t & 2047;
        cs[bb][k] = (k < LAT) ? lat[(bb0 + bb) * LAT + k]
                              : freq[(bb0 + bb) * FREQN + k - LAT];
    }
    __syncthreads();
    float a0 = 0.f, a1 = 0.f, a2 = 0.f, a3 = 0.f;
#pragma unroll 4
    for (int k = 0; k < CAT; k++) {
        float w = w1[(size_t)k * CAT + j];
        a0 += cs[0][k] * w; a1 += cs[1][k] * w;
        a2 += cs[2][k] * w; a3 += cs[3][k] * w;
    }
    float bb = b1[j];
    t1[(bb0 + 0) * CAT + j] = leaky(a0 + bb);
    t1[(bb0 + 1) * CAT + j] = leaky(a1 + bb);
    t1[(bb0 + 2) * CAT + j] = leaky(a2 + bb);
    t1[(bb0 + 3) * CAT + j] = leaky(a3 + bb);
}

// ---------------- otl phase B: lat' = cat@ws + bs + t1@w2 + b2 ----------------
// grid (4 jblocks, 8 batchgroups of 2), block 128
__global__ __launch_bounds__(128) void k_cat_o(const float* __restrict__ lat,
                                               const float* __restrict__ freq,
                                               const float* __restrict__ t1,
                                               const float* __restrict__ w2,
                                               const float* __restrict__ b2,
                                               const float* __restrict__ ws,
                                               const float* __restrict__ bs,
                                               float* __restrict__ latout) {
    __shared__ float cs[2][CAT];
    __shared__ float ts[2][CAT];
    int j = blockIdx.x * 128 + threadIdx.x;
    int bb0 = blockIdx.y * 2;
    for (int t = threadIdx.x; t < 2 * CAT; t += 128) {
        int bb = t >> 11, k = t & 2047;
        cs[bb][k] = (k < LAT) ? lat[(bb0 + bb) * LAT + k]
                              : freq[(bb0 + bb) * FREQN + k - LAT];
        ts[bb][k] = t1[(bb0 + bb) * CAT + k];
    }
    __syncthreads();
    float a0 = 0.f, a1 = 0.f;
#pragma unroll 4
    for (int k = 0; k < CAT; k++) {
        float a = ws[(size_t)k * LAT + j];
        float c = w2[(size_t)k * LAT + j];
        a0 += cs[0][k] * a + ts[0][k] * c;
        a1 += cs[1][k] * a + ts[1][k] * c;
    }
    float bb = bs[j] + b2[j];
    latout[(bb0 + 0) * LAT + j] = a0 + bb;
    latout[(bb0 + 1) * LAT + j] = a1 + bb;
}

// ---------------- final projection ----------------
__global__ __launch_bounds__(128) void k_final(const float* __restrict__ lat,
                                               const float* __restrict__ w,
                                               const float* __restrict__ bb,
                                               float* __restrict__ out) {
    __shared__ float xs[4][LAT];
    int j = blockIdx.x * 128 + threadIdx.x;
    int bb0 = blockIdx.y * 4;
    for (int t = threadIdx.x; t < 4 * LAT; t += 128)
        xs[t >> 9][t & 511] = lat[(bb0 + (t >> 9)) * LAT + (t & 511)];
    __syncthreads();
    float a0 = 0.f, a1 = 0.f, a2 = 0.f, a3 = 0.f;
#pragma unroll 8
    for (int k = 0; k < LAT; k++) {
        float wv = w[(size_t)k * LAT + j];
        a0 += xs[0][k] * wv; a1 += xs[1][k] * wv;
        a2 += xs[2][k] * wv; a3 += xs[3][k] * wv;
    }
    float bv = bb[j];
    out[(bb0 + 0) * LAT + j] = a0 + bv;
    out[(bb0 + 1) * LAT + j] = a1 + bv;
    out[(bb0 + 2) * LAT + j] = a2 + bv;
    out[(bb0 + 3) * LAT + j] = a3 + bv;
}

// ---------------- launch ----------------
extern "C" void kernel_launch(void* const* d_in, const int* in_sizes, int n_in,
                              void* d_out, int out_size) {
    const float* x       = (const float*)d_in[0];
    const float* inj_lat = (const float*)d_in[1];
    const float* w_in    = (const float*)d_in[2];
    const float* b_in    = (const float*)d_in[3];
    const float* fl_w1   = (const float*)d_in[4];
    const float* fl_b1   = (const float*)d_in[5];
    const float* fl_w2   = (const float*)d_in[6];
    const float* fl_b2   = (const float*)d_in[7];
    const float* fl_ws   = (const float*)d_in[8];
    const float* fl_bs   = (const float*)d_in[9];
    const float* dyn_w   = (const float*)d_in[10];
    const float* dyn_b   = (const float*)d_in[11];
    const float* pe      = (const float*)d_in[12];
    const float* otl_w1  = (const float*)d_in[13];
    const float* otl_b1  = (const float*)d_in[14];
    const float* otl_w2  = (const float*)d_in[15];
    const float* otl_b2  = (const float*)d_in[16];
    const float* otl_ws  = (const float*)d_in[17];
    const float* otl_bs  = (const float*)d_in[18];
    const float* ltl_w   = (const float*)d_in[19];
    const float* ltl_b   = (const float*)d_in[20];

    float *chain, *hbuf, *P, *img0, *img1, *Z, *AT, *bfold, *meanb, *rstdb, *HS, *freqb, *latA, *latB, *t1b;
    cudaGetSymbolAddress((void**)&chain, g_chain);
    cudaGetSymbolAddress((void**)&hbuf, g_hbuf);
    cudaGetSymbolAddress((void**)&P, g_P);
    cudaGetSymbolAddress((void**)&img0, g_img0);
    cudaGetSymbolAddress((void**)&img1, g_img1);
    cudaGetSymbolAddress((void**)&Z, g_Z);
    cudaGetSymbolAddress((void**)&AT, g_AT);
    cudaGetSymbolAddress((void**)&bfold, g_bfold);
    cudaGetSymbolAddress((void**)&meanb, g_mean);
    cudaGetSymbolAddress((void**)&rstdb, g_rstd);
    cudaGetSymbolAddress((void**)&HS, g_HS);
    cudaGetSymbolAddress((void**)&freqb, g_freq);
    cudaGetSymbolAddress((void**)&latA, g_latA);
    cudaGetSymbolAddress((void**)&latB, g_latB);
    cudaGetSymbolAddress((void**)&t1b, g_t1);

    cudaMemsetAsync(latA, 0, BATCH * LAT * sizeof(float));

    k_inimg<<<(BATCH * NF * HW + 255) / 256, 256>>>(x, w_in, b_in, img0);

    // latent chain (image-independent) hoisted up front
    {
        const float* cin = inj_lat;
        for (int t = 0; t < 4; t++) {
            float* cout = chain + t * BATCH * LAT;
            k_lin_h<<<dim3(4, 4), 128>>>(cin, fl_w1, fl_b1, hbuf);
            k_lin_o<<<dim3(4, 4), 128>>>(cin, hbuf, fl_ws, fl_w2, fl_bs, fl_b2, cout);
            cin = cout;
        }
    }

    // all 4 iterations' dynamic params in ONE pass over dyn_w
    k_dyngemm<<<(P_DYN + 127) / 128, dim3(32, 8)>>>(chain, dyn_w, dyn_b, P);

    float* cur = img0; float* nxt = img1;
    float* lcur = latA; float* lnxt = latB;
    for (int c = 0; c < NC; c++) {
        const float* Pc = P + (size_t)c * BATCH * P_DYN;
        k_zstats<<<dim3(FIN, BATCH), 256>>>(cur, Z, meanb, rstdb);
        k_fold<<<dim3(64, BATCH), FIN>>>(Pc, meanb, rstdb, AT, bfold);
        k_g1_mma<<<dim3(HW / 128, BATCH), 256>>>(AT, Z, bfold, HS);
        k_g2<<<dim3(HW / 128, BATCH), dim3(32, 8)>>>(Pc, HS, nxt);
        k_freq<<<dim3(NF, BATCH), 256>>>(nxt, pe, freqb);
        k_cat_h<<<dim3(16, 4), 128>>>(lcur, freqb, otl_w1 + (size_t)c * CAT * CAT,
                                      otl_b1 + c * CAT, t1b);
        k_cat_o<<<dim3(4, 8), 128>>>(lcur, freqb, t1b,
                                     otl_w2 + (size_t)c * CAT * LAT, otl_b2 + c * LAT,
                                     otl_ws + (size_t)c * CAT * LAT, otl_bs + c * LAT,
                                     lnxt);
        { float* t = cur; cur = nxt; nxt = t; }
        { float* t = lcur; lcur = lnxt; lnxt = t; }
    }
    k_final<<<dim3(4, 4), 128>>>(lcur, ltl_w, ltl_b, (float*)d_out);
}

// round 4
// speedup vs baseline: 2.1241x; 1.7407x over previous
#include <cuda_runtime.h>
#include <cuda_fp16.h>
#include <cuda_bf16.h>
#include <math.h>

// ---------------- constants ----------------
#define BATCH 16
#define NF 64
#define LAT 512
#define IMGD 64
#define HW 4096          // 64*64
#define NC 4
#define CF 9
#define FIN 576          // NF*CF
#define NFREQ 6
#define FCH 24           // 4*NFREQ
#define FREQN 1536       // NF*FCH
#define CAT 2048         // LAT + NF*FCH
#define P_DYN 78016
// P layout offsets
#define OFF_KIN 0        // [64][576]
#define OFF_BIN 36864    // [64]
#define OFF_KOUT 36928   // [64][64]
#define OFF_BOUT 41024   // [64]
#define OFF_KSK 41088    // [64][576]
#define OFF_BSK 77952    // [64]

// ---------------- scratch (device globals; no allocation) ----------------
__device__ float g_chain[4 * BATCH * LAT];
__device__ float g_hpart[8 * BATCH * LAT];
__device__ float g_opart[8 * BATCH * LAT];
__device__ float g_t1part[8 * BATCH * CAT];
__device__ float g_latpart[8 * BATCH * LAT];
__device__ float g_P[64ull * P_DYN];
__device__ float g_img0[BATCH * NF * HW];
__device__ float g_img1[BATCH * NF * HW];
__device__ __half g_Zh[(size_t)BATCH * FIN * HW];
__device__ float g_AT[BATCH * FIN * 128];
__device__ float g_bfold[BATCH * 128];
__device__ float g_mean[BATCH * FIN];
__device__ float g_rstd[BATCH * FIN];
__device__ float g_HS[(size_t)BATCH * 128 * HW];
__device__ float g_freq[BATCH * FREQN];
__device__ float g_latA[BATCH * LAT];
__device__ float g_latB[BATCH * LAT];

__device__ __forceinline__ float leaky(float v) { return v > 0.f ? v : 0.2f * v; }

__device__ __forceinline__ unsigned f2tf(float v) {
    unsigned r;
    asm("cvt.rna.tf32.f32 %0, %1;" : "=r"(r) : "f"(v));
    return r;
}

__device__ __forceinline__ uint4 h4_to_tf(uint2 v) {
    __half2 a = *(__half2*)&v.x, b = *(__half2*)&v.y;
    float2 fa = __half22float2(a), fb = __half22float2(b);
    return make_uint4(f2tf(fa.x), f2tf(fa.y), f2tf(fb.x), f2tf(fb.y));
}

// ---------------- input image projection ----------------
__global__ void k_inimg(const float* __restrict__ x, const float* __restrict__ w_in,
                        const float* __restrict__ b_in, float* __restrict__ img) {
    int idx = blockIdx.x * 256 + threadIdx.x;
    if (idx >= BATCH * NF * HW) return;
    int p = idx & (HW - 1);
    int o = (idx >> 12) & 63;
    int b = idx >> 18;
    const float* xb = x + (size_t)b * 3 * HW;
    float v = b_in[o] + w_in[o * 3 + 0] * xb[p] + w_in[o * 3 + 1] * xb[HW + p]
            + w_in[o * 3 + 2] * xb[2 * HW + p];
    img[idx] = v;
}

// ---------------- generic 8-way partial reduce ----------------
__global__ void k_fin8(const float* __restrict__ part, float* __restrict__ out, int n) {
    int i = blockIdx.x * 256 + threadIdx.x;
    if (i >= n) return;
    float s = 0.f;
#pragma unroll
    for (int p = 0; p < 8; p++) s += part[p * n + i];
    out[i] = s;
}

// ---------------- lin_res 512 phase 1 (split-k partials of x@w1) ----------------
// grid (4 jblocks, 8 kslices), block 128; all 16 batches per block
__global__ __launch_bounds__(128) void k_lin_h2(const float* __restrict__ in,
                                                const float* __restrict__ w1,
                                                float* __restrict__ hpart) {
    __shared__ float xs[16][64];
    int j = blockIdx.x * 128 + threadIdx.x;
    int k0 = blockIdx.y * 64;
    for (int t = threadIdx.x; t < 16 * 64; t += 128)
        xs[t >> 6][t & 63] = in[(t >> 6) * LAT + k0 + (t & 63)];
    __syncthreads();
    float acc[16];
#pragma unroll
    for (int bb = 0; bb < 16; bb++) acc[bb] = 0.f;
#pragma unroll 4
    for (int kk = 0; kk < 64; kk++) {
        float w = w1[(size_t)(k0 + kk) * LAT + j];
#pragma unroll
        for (int bb = 0; bb < 16; bb++) acc[bb] += xs[bb][kk] * w;
    }
#pragma unroll
    for (int bb = 0; bb < 16; bb++)
        hpart[(blockIdx.y * 16 + bb) * LAT + j] = acc[bb];
}

// ---------------- lin_res 512 phase 2 (x@ws + h@w2, h reduced inline) ----------------
__global__ __launch_bounds__(128) void k_lin_o2(const float* __restrict__ in,
                                                const float* __restrict__ hpart,
                                                const float* __restrict__ b1,
                                                const float* __restrict__ ws,
                                                const float* __restrict__ w2,
                                                const float* __restrict__ bs,
                                                const float* __restrict__ b2,
                                                float* __restrict__ opart) {
    __shared__ float xs[16][64];
    __shared__ float hs[16][64];
    int j = blockIdx.x * 128 + threadIdx.x;
    int k0 = blockIdx.y * 64;
    for (int t = threadIdx.x; t < 16 * 64; t += 128) {
        int bb = t >> 6, kk = t & 63;
        int k = k0 + kk;
        xs[bb][kk] = in[bb * LAT + k];
        float s = b1[k];
#pragma unroll
        for (int p = 0; p < 8; p++) s += hpart[(p * 16 + bb) * LAT + k];
        hs[bb][kk] = leaky(s);
    }
    __syncthreads();
    float acc[16];
#pragma unroll
    for (int bb = 0; bb < 16; bb++) acc[bb] = 0.f;
#pragma unroll 4
    for (int kk = 0; kk < 64; kk++) {
        float a = ws[(size_t)(k0 + kk) * LAT + j];
        float c = w2[(size_t)(k0 + kk) * LAT + j];
#pragma unroll
        for (int bb = 0; bb < 16; bb++) acc[bb] += xs[bb][kk] * a + hs[bb][kk] * c;
    }
    float bias = (blockIdx.y == 0) ? (bs[j] + b2[j]) : 0.f;
#pragma unroll
    for (int bb = 0; bb < 16; bb++)
        opart[(blockIdx.y * 16 + bb) * LAT + j] = acc[bb] + bias;
}

// ---------------- dyn params GEMM: [64,512] @ [512,78016] + bias ----------------
__global__ __launch_bounds__(256) void k_dyngemm(const float* __restrict__ lat,
                                                 const float* __restrict__ W,
                                                 const float* __restrict__ bias,
                                                 float* __restrict__ P) {
    __shared__ float ls[32][65];
    int tid = threadIdx.y * 32 + threadIdx.x;
    int col0 = blockIdx.x * 128 + threadIdx.x * 4;
    bool ok = col0 < P_DYN;
    float acc[8][4];
#pragma unroll
    for (int r = 0; r < 8; r++)
#pragma unroll
        for (int c = 0; c < 4; c++) acc[r][c] = 0.f;

    for (int k0 = 0; k0 < LAT; k0 += 32) {
#pragma unroll
        for (int t = 0; t < 8; t++) {
            int idx = tid + t * 256;
            int m = idx >> 5, kk = idx & 31;
            ls[kk][m] = lat[m * LAT + k0 + kk];
        }
        __syncthreads();
        if (ok) {
#pragma unroll
            for (int kk = 0; kk < 32; kk++) {
                float4 w = *(const float4*)(W + (size_t)(k0 + kk) * P_DYN + col0);
#pragma unroll
                for (int r = 0; r < 8; r++) {
                    float l = ls[kk][threadIdx.y * 8 + r];
                    acc[r][0] += l * w.x; acc[r][1] += l * w.y;
                    acc[r][2] += l * w.z; acc[r][3] += l * w.w;
                }
            }
        }
        __syncthreads();
    }
    if (ok) {
        float4 bv = *(const float4*)(bias + col0);
#pragma unroll
        for (int r = 0; r < 8; r++) {
            int m = threadIdx.y * 8 + r;
            float4 o;
            o.x = acc[r][0] + bv.x; o.y = acc[r][1] + bv.y;
            o.z = acc[r][2] + bv.z; o.w = acc[r][3] + bv.w;
            *(float4*)(P + (size_t)m * P_DYN + col0) = o;
        }
    }
}

// ---------------- perceive + stats (Z (fp16) materialize + mean/rstd) ----------------
__global__ void k_zstats(const float* __restrict__ img, __half* __restrict__ Z,
                         float* __restrict__ mean, float* __restrict__ rstd) {
    int b = blockIdx.y;
    int i = blockIdx.x;                 // 0..575
    int g = i >> 6, f = i & 63;
    const float* O = img + (size_t)(b * NF + f) * HW;
    __half* zrow = Z + ((size_t)b * FIN + i) * HW;
    double s1 = 0.0, s2 = 0.0;

    if (g == 0) {
        for (int p = threadIdx.x; p < HW; p += 256) {
            float v = O[p];
            zrow[p] = __float2half(v); s1 += v; s2 += (double)v * v;
        }
    } else {
        int d = 1 << ((g - 1) >> 1);
        bool isSX = ((g - 1) & 1) == 0;
        for (int p = threadIdx.x; p < HW; p += 256) {
            int h = p >> 6, w = p & 63;
            int hm = h - d, hp = h + d, wm = w - d, wp = w + d;
            bool hmv = hm >= 0, hpv = hp < IMGD, wmv = wm >= 0, wpv = wp < IMGD;
            float v;
            if (isSX) {
                float t = 0.f;
                if (wmv) {
                    if (hmv) t -= O[hm * IMGD + wm];
                    t -= 2.f * O[h * IMGD + wm];
                    if (hpv) t -= O[hp * IMGD + wm];
                }
                if (wpv) {
                    if (hmv) t += O[hm * IMGD + wp];
                    t += 2.f * O[h * IMGD + wp];
                    if (hpv) t += O[hp * IMGD + wp];
                }
                v = 0.125f * t;
            } else {
                float t = 0.f;
                if (hmv) {
                    if (wmv) t -= O[hm * IMGD + wm];
                    t -= 2.f * O[hm * IMGD + w];
                    if (wpv) t -= O[hm * IMGD + wp];
                }
                if (hpv) {
                    if (wmv) t += O[hp * IMGD + wm];
                    t += 2.f * O[hp * IMGD + w];
                    if (wpv) t += O[hp * IMGD + wp];
                }
                v = 0.125f * t;
            }
            zrow[p] = __float2half(v); s1 += v; s2 += (double)v * v;
        }
    }
    __shared__ double rs1[8], rs2[8];
    int lane = threadIdx.x & 31, wid = threadIdx.x >> 5;
#pragma unroll
    for (int off = 16; off; off >>= 1) {
        s1 += __shfl_down_sync(0xffffffffu, s1, off);
        s2 += __shfl_down_sync(0xffffffffu, s2, off);
    }
    if (lane == 0) { rs1[wid] = s1; rs2[wid] = s2; }
    __syncthreads();
    if (threadIdx.x == 0) {
        double t1 = 0.0, t2 = 0.0;
        for (int w = 0; w < 8; w++) { t1 += rs1[w]; t2 += rs2[w]; }
        double m = t1 / 4096.0;
        double var = t2 / 4096.0 - m * m;
        mean[b * FIN + i] = (float)m;
        rstd[b * FIN + i] = 1.0f / sqrtf((float)var + 1e-5f);
    }
}

// ---------------- fold inorm into dynamic weights ----------------
__global__ void k_fold(const float* __restrict__ P, const float* __restrict__ mean,
                       const float* __restrict__ rstd, float* __restrict__ AT,
                       float* __restrict__ bfold) {
    int b = blockIdx.y, f = blockIdx.x;
    const float* pb = P + (size_t)b * P_DYN;
    int i = threadIdx.x;  // 0..575
    float r = rstd[b * FIN + i], m = mean[b * FIN + i];
    float win = pb[OFF_KIN + f * FIN + i] * r;
    float wsk = pb[OFF_KSK + f * FIN + i] * r;
    AT[(size_t)b * FIN * 128 + i * 128 + f] = win;
    AT[(size_t)b * FIN * 128 + i * 128 + 64 + f] = wsk;
    float t1 = win * m, t2 = wsk * m;
    __shared__ float r1[18], r2[18];
    int lane = threadIdx.x & 31, wid = threadIdx.x >> 5;
#pragma unroll
    for (int off = 16; off; off >>= 1) {
        t1 += __shfl_down_sync(0xffffffffu, t1, off);
        t2 += __shfl_down_sync(0xffffffffu, t2, off);
    }
    if (lane == 0) { r1[wid] = t1; r2[wid] = t2; }
    __syncthreads();
    if (threadIdx.x == 0) {
        float s1 = 0.f, s2 = 0.f;
        for (int w = 0; w < 18; w++) { s1 += r1[w]; s2 += r2[w]; }
        bfold[b * 128 + f] = pb[OFF_BIN + f] - s1;
        bfold[b * 128 + 64 + f] = pb[OFF_BSK + f] - s2;
    }
}

// ---------------- main GEMM via tf32 mma.sync: [128,576]@[576,4096] per batch ----------------
__global__ __launch_bounds__(256) void k_g1_mma(const float* __restrict__ AT,
                                                const __half* __restrict__ Z,
                                                const float* __restrict__ bfold,
                                                float* __restrict__ HS) {
    __shared__ unsigned As[2][16][136];
    __shared__ unsigned Bs[2][16][136];
    int b = blockIdx.y;
    int p0 = blockIdx.x * 128;
    const float* At = AT + (size_t)b * FIN * 128;
    const __half* Zb = Z + (size_t)b * FIN * HW;
    int tid = threadIdx.x, lane = tid & 31, warp = tid >> 5;
    int ch0 = (warp & 1) * 64;
    int px0 = (warp >> 1) * 32;
    int r = lane >> 2, cc = lane & 3;

    float acc[4][4][4];
#pragma unroll
    for (int mt = 0; mt < 4; mt++)
#pragma unroll
        for (int nt = 0; nt < 4; nt++)
#pragma unroll
            for (int q = 0; q < 4; q++) acc[mt][nt][q] = 0.f;

    int rowL = tid >> 5;        // 0..7
    int colL = lane * 4;        // 0..124

    // stage chunk 0
    float4 va0 = *(const float4*)(At + (size_t)rowL * 128 + colL);
    float4 va1 = *(const float4*)(At + (size_t)(rowL + 8) * 128 + colL);
    uint2 vb0 = *(const uint2*)(Zb + (size_t)rowL * HW + p0 + colL);
    uint2 vb1 = *(const uint2*)(Zb + (size_t)(rowL + 8) * HW + p0 + colL);
    *(uint4*)&As[0][rowL][colL]     = make_uint4(f2tf(va0.x), f2tf(va0.y), f2tf(va0.z), f2tf(va0.w));
    *(uint4*)&As[0][rowL + 8][colL] = make_uint4(f2tf(va1.x), f2tf(va1.y), f2tf(va1.z), f2tf(va1.w));
    *(uint4*)&Bs[0][rowL][colL]     = h4_to_tf(vb0);
    *(uint4*)&Bs[0][rowL + 8][colL] = h4_to_tf(vb1);
    __syncthreads();

    for (int t = 0; t < 36; t++) {
        int cur = t & 1;
        float4 na0, na1;
        uint2 nb0, nb1;
        if (t < 35) {
            int i0 = (t + 1) * 16;
            na0 = *(const float4*)(At + (size_t)(i0 + rowL) * 128 + colL);
            na1 = *(const float4*)(At + (size_t)(i0 + rowL + 8) * 128 + colL);
            nb0 = *(const uint2*)(Zb + (size_t)(i0 + rowL) * HW + p0 + colL);
            nb1 = *(const uint2*)(Zb + (size_t)(i0 + rowL + 8) * HW + p0 + colL);
        }
#pragma unroll
        for (int ks = 0; ks < 2; ks++) {
            int kk = ks * 8;
            unsigned af[4][4], bf[4][2];
#pragma unroll
            for (int mt = 0; mt < 4; mt++) {
                int m = ch0 + mt * 16;
                af[mt][0] = As[cur][kk + cc][m + r];
                af[mt][1] = As[cur][kk + cc][m + r + 8];
                af[mt][2] = As[cur][kk + cc + 4][m + r];
                af[mt][3] = As[cur][kk + cc + 4][m + r + 8];
            }
#pragma unroll
            for (int nt = 0; nt < 4; nt++) {
                int n = px0 + nt * 8 + r;
                bf[nt][0] = Bs[cur][kk + cc][n];
                bf[nt][1] = Bs[cur][kk + cc + 4][n];
            }
#pragma unroll
            for (int mt = 0; mt < 4; mt++)
#pragma unroll
                for (int nt = 0; nt < 4; nt++) {
                    asm volatile(
                        "mma.sync.aligned.m16n8k8.row.col.f32.tf32.tf32.f32 "
                        "{%0,%1,%2,%3}, {%4,%5,%6,%7}, {%8,%9}, {%0,%1,%2,%3};"
                        : "+f"(acc[mt][nt][0]), "+f"(acc[mt][nt][1]),
                          "+f"(acc[mt][nt][2]), "+f"(acc[mt][nt][3])
                        : "r"(af[mt][0]), "r"(af[mt][1]), "r"(af[mt][2]), "r"(af[mt][3]),
                          "r"(bf[nt][0]), "r"(bf[nt][1]));
                }
        }
        if (t < 35) {
            int nxt = cur ^ 1;
            *(uint4*)&As[nxt][rowL][colL]     = make_uint4(f2tf(na0.x), f2tf(na0.y), f2tf(na0.z), f2tf(na0.w));
            *(uint4*)&As[nxt][rowL + 8][colL] = make_uint4(f2tf(na1.x), f2tf(na1.y), f2tf(na1.z), f2tf(na1.w));
            *(uint4*)&Bs[nxt][rowL][colL]     = h4_to_tf(nb0);
            *(uint4*)&Bs[nxt][rowL + 8][colL] = h4_to_tf(nb1);
        }
        __syncthreads();
    }

    // epilogue: bias + leaky(rows<64) + store
#pragma unroll
    for (int mt = 0; mt < 4; mt++) {
        int row0 = ch0 + mt * 16 + r;
        int row1 = row0 + 8;
        float bi0 = bfold[b * 128 + row0];
        float bi1 = bfold[b * 128 + row1];
        bool lk = (ch0 == 0);
#pragma unroll
        for (int nt = 0; nt < 4; nt++) {
            int gcol = p0 + px0 + nt * 8 + 2 * cc;
            float v0 = acc[mt][nt][0] + bi0, v1 = acc[mt][nt][1] + bi0;
            float v2 = acc[mt][nt][2] + bi1, v3 = acc[mt][nt][3] + bi1;
            if (lk) { v0 = leaky(v0); v1 = leaky(v1); v2 = leaky(v2); v3 = leaky(v3); }
            *(float2*)(HS + ((size_t)b * 128 + row0) * HW + gcol) = make_float2(v0, v1);
            *(float2*)(HS + ((size_t)b * 128 + row1) * HW + gcol) = make_float2(v2, v3);
        }
    }
}

// ---------------- second GEMM + skip: out = k_out@H + b_out + S ----------------
__global__ __launch_bounds__(256) void k_g2(const float* __restrict__ P,
                                            const float* __restrict__ HS,
                                            float* __restrict__ outimg) {
    __shared__ float ko[64][65];
    int b = blockIdx.y;
    const float* pb = P + (size_t)b * P_DYN;
    int tid = threadIdx.y * 32 + threadIdx.x;
    for (int idx = tid; idx < 4096; idx += 256) ko[idx >> 6][idx & 63] = pb[OFF_KOUT + idx];
    __syncthreads();

    int col0 = blockIdx.x * 128 + threadIdx.x * 4;
    int r0 = threadIdx.y * 8;
    const float* Hb = HS + (size_t)b * 128 * HW;
    float acc[8][4];
#pragma unroll
    for (int r = 0; r < 8; r++)
#pragma unroll
        for (int c = 0; c < 4; c++) acc[r][c] = 0.f;

#pragma unroll 4
    for (int f = 0; f < 64; f++) {
        float4 h = *(const float4*)(Hb + (size_t)f * HW + col0);
#pragma unroll
        for (int r = 0; r < 8; r++) {
            float w = ko[r0 + r][f];
            acc[r][0] += w * h.x; acc[r][1] += w * h.y;
            acc[r][2] += w * h.z; acc[r][3] += w * h.w;
        }
    }
#pragma unroll
    for (int r = 0; r < 8; r++) {
        int o = r0 + r;
        float bo = pb[OFF_BOUT + o];
        float4 s = *(const float4*)(Hb + (size_t)(64 + o) * HW + col0);
        float4 v;
        v.x = acc[r][0] + bo + s.x; v.y = acc[r][1] + bo + s.y;
        v.z = acc[r][2] + bo + s.z; v.w = acc[r][3] + bo + s.w;
        *(float4*)(outimg + ((size_t)b * NF + o) * HW + col0) = v;
    }
}

// ---------------- frequency readout ----------------
__global__ void k_freq(const float* __restrict__ img, const float* __restrict__ pe,
                       float* __restrict__ freqout) {
    int b = blockIdx.y, ch = blockIdx.x;
    const float* O = img + (size_t)(b * NF + ch) * HW;
    float acc[FCH];
#pragma unroll
    for (int f = 0; f < FCH; f++) acc[f] = 0.f;
    for (int p = threadIdx.x; p < HW; p += 256) {
        float v = O[p];
#pragma unroll
        for (int f = 0; f < FCH; f++) acc[f] += v * pe[f * HW + p];
    }
    __shared__ float red[FCH][9];
    int lane = threadIdx.x & 31, wid = threadIdx.x >> 5;
#pragma unroll
    for (int f = 0; f < FCH; f++) {
        float v = acc[f];
#pragma unroll
        for (int off = 16; off; off >>= 1) v += __shfl_down_sync(0xffffffffu, v, off);
        if (lane == 0) red[f][wid] = v;
    }
    __syncthreads();
    if (threadIdx.x < FCH) {
        float s = 0.f;
        for (int w = 0; w < 8; w++) s += red[threadIdx.x][w];
        freqout[b * FREQN + ch * FCH + threadIdx.x] = s * (1.0f / 4096.0f);
    }
}

// ---------------- otl phase A: split-k partials of cat @ w1 ----------------
// grid (16 jblocks, 8 kslices), block 128; 16 batches per block
__global__ __launch_bounds__(128) void k_cat_h2(const float* __restrict__ latfin,
                                                const float* __restrict__ freq,
                                                const float* __restrict__ w1,
                                                float* __restrict__ t1part) {
    __shared__ float cs[16][256];
    int j = blockIdx.x * 128 + threadIdx.x;
    int k0 = blockIdx.y * 256;
    for (int t = threadIdx.x; t < 16 * 256; t += 128) {
        int bb = t >> 8, kk = t & 255;
        int k = k0 + kk;
        cs[bb][kk] = (k < LAT) ? latfin[bb * LAT + k] : freq[bb * FREQN + k - LAT];
    }
    __syncthreads();
    float acc[16];
#pragma unroll
    for (int bb = 0; bb < 16; bb++) acc[bb] = 0.f;
#pragma unroll 4
    for (int kk = 0; kk < 256; kk++) {
        float w = w1[(size_t)(k0 + kk) * CAT + j];
#pragma unroll
        for (int bb = 0; bb < 16; bb++) acc[bb] += cs[bb][kk] * w;
    }
#pragma unroll
    for (int bb = 0; bb < 16; bb++)
        t1part[(blockIdx.y * 16 + bb) * CAT + j] = acc[bb];
}

// ---------------- otl phase B: cat@ws + t1@w2 (t1 reduced+leaky inline) ----------------
// grid (4 jblocks, 8 kslices), block 128
__global__ __launch_bounds__(128) void k_cat_o2(const float* __restrict__ latfin,
                                                const float* __restrict__ freq,
                                                const float* __restrict__ t1part,
                                                const float* __restrict__ b1,
                                                const float* __restrict__ w2,
                                                const float* __restrict__ b2,
                                                const float* __restrict__ ws,
                                                const float* __restrict__ bs,
                                                float* __restrict__ latpart) {
    __shared__ float cs[16][256];
    __shared__ float ts[16][256];
    int j = blockIdx.x * 128 + threadIdx.x;
    int k0 = blockIdx.y * 256;
    for (int t = threadIdx.x; t < 16 * 256; t += 128) {
        int bb = t >> 8, kk = t & 255;
        int k = k0 + kk;
        cs[bb][kk] = (k < LAT) ? latfin[bb * LAT + k] : freq[bb * FREQN + k - LAT];
        float s = b1[k];
#pragma unroll
        for (int p = 0; p < 8; p++) s += t1part[(p * 16 + bb) * CAT + k];
        ts[bb][kk] = leaky(s);
    }
    __syncthreads();
    float acc[16];
#pragma unroll
    for (int bb = 0; bb < 16; bb++) acc[bb] = 0.f;
#pragma unroll 4
    for (int kk = 0; kk < 256; kk++) {
        float a = ws[(size_t)(k0 + kk) * LAT + j];
        float c = w2[(size_t)(k0 + kk) * LAT + j];
#pragma unroll
        for (int bb = 0; bb < 16; bb++) acc[bb] += cs[bb][kk] * a + ts[bb][kk] * c;
    }
    float bias = (blockIdx.y == 0) ? (bs[j] + b2[j]) : 0.f;
#pragma unroll
    for (int bb = 0; bb < 16; bb++)
        latpart[(blockIdx.y * 16 + bb) * LAT + j] = acc[bb] + bias;
}

// ---------------- final projection ----------------
__global__ __launch_bounds__(128) void k_final(const float* __restrict__ lat,
                                               const float* __restrict__ w,
                                               const float* __restrict__ bb,
                                               float* __restrict__ out) {
    __shared__ float xs[4][LAT];
    int j = blockIdx.x * 128 + threadIdx.x;
    int bb0 = blockIdx.y * 4;
    for (int t = threadIdx.x; t < 4 * LAT; t += 128)
        xs[t >> 9][t & 511] = lat[(bb0 + (t >> 9)) * LAT + (t & 511)];
    __syncthreads();
    float a0 = 0.f, a1 = 0.f, a2 = 0.f, a3 = 0.f;
#pragma unroll 8
    for (int k = 0; k < LAT; k++) {
        float wv = w[(size_t)k * LAT + j];
        a0 += xs[0][k] * wv; a1 += xs[1][k] * wv;
        a2 += xs[2][k] * wv; a3 += xs[3][k] * wv;
    }
    float bv = bb[j];
    out[(bb0 + 0) * LAT + j] = a0 + bv;
    out[(bb0 + 1) * LAT + j] = a1 + bv;
    out[(bb0 + 2) * LAT + j] = a2 + bv;
    out[(bb0 + 3) * LAT + j] = a3 + bv;
}

// ---------------- launch ----------------
extern "C" void kernel_launch(void* const* d_in, const int* in_sizes, int n_in,
                              void* d_out, int out_size) {
    const float* x       = (const float*)d_in[0];
    const float* inj_lat = (const float*)d_in[1];
    const float* w_in    = (const float*)d_in[2];
    const float* b_in    = (const float*)d_in[3];
    const float* fl_w1   = (const float*)d_in[4];
    const float* fl_b1   = (const float*)d_in[5];
    const float* fl_w2   = (const float*)d_in[6];
    const float* fl_b2   = (const float*)d_in[7];
    const float* fl_ws   = (const float*)d_in[8];
    const float* fl_bs   = (const float*)d_in[9];
    const float* dyn_w   = (const float*)d_in[10];
    const float* dyn_b   = (const float*)d_in[11];
    const float* pe      = (const float*)d_in[12];
    const float* otl_w1  = (const float*)d_in[13];
    const float* otl_b1  = (const float*)d_in[14];
    const float* otl_w2  = (const float*)d_in[15];
    const float* otl_b2  = (const float*)d_in[16];
    const float* otl_ws  = (const float*)d_in[17];
    const float* otl_bs  = (const float*)d_in[18];
    const float* ltl_w   = (const float*)d_in[19];
    const float* ltl_b   = (const float*)d_in[20];

    float *chain, *hpart, *opart, *t1part, *latpart, *P, *img0, *img1, *AT, *bfold,
          *meanb, *rstdb, *HS, *freqb, *latA, *latB;
    __half* Zh;
    cudaGetSymbolAddress((void**)&chain, g_chain);
    cudaGetSymbolAddress((void**)&hpart, g_hpart);
    cudaGetSymbolAddress((void**)&opart, g_opart);
    cudaGetSymbolAddress((void**)&t1part, g_t1part);
    cudaGetSymbolAddress((void**)&latpart, g_latpart);
    cudaGetSymbolAddress((void**)&P, g_P);
    cudaGetSymbolAddress((void**)&img0, g_img0);
    cudaGetSymbolAddress((void**)&img1, g_img1);
    cudaGetSymbolAddress((void**)&Zh, g_Zh);
    cudaGetSymbolAddress((void**)&AT, g_AT);
    cudaGetSymbolAddress((void**)&bfold, g_bfold);
    cudaGetSymbolAddress((void**)&meanb, g_mean);
    cudaGetSymbolAddress((void**)&rstdb, g_rstd);
    cudaGetSymbolAddress((void**)&HS, g_HS);
    cudaGetSymbolAddress((void**)&freqb, g_freq);
    cudaGetSymbolAddress((void**)&latA, g_latA);
    cudaGetSymbolAddress((void**)&latB, g_latB);

    cudaMemsetAsync(latA, 0, BATCH * LAT * sizeof(float));

    k_inimg<<<(BATCH * NF * HW + 255) / 256, 256>>>(x, w_in, b_in, img0);

    // latent chain (image-independent), split-k
    {
        const float* cin = inj_lat;
        for (int t = 0; t < 4; t++) {
            float* cout = chain + t * BATCH * LAT;
            k_lin_h2<<<dim3(4, 8), 128>>>(cin, fl_w1, hpart);
            k_lin_o2<<<dim3(4, 8), 128>>>(cin, hpart, fl_b1, fl_ws, fl_w2, fl_bs, fl_b2, opart);
            k_fin8<<<BATCH * LAT / 256, 256>>>(opart, cout, BATCH * LAT);
            cin = cout;
        }
    }

    // all 4 iterations' dynamic params in ONE pass over dyn_w
    k_dyngemm<<<(P_DYN + 127) / 128, dim3(32, 8)>>>(chain, dyn_w, dyn_b, P);

    float* cur = img0; float* nxt = img1;
    float* lcur = latA; float* lnxt = latB;
    for (int c = 0; c < NC; c++) {
        const float* Pc = P + (size_t)c * BATCH * P_DYN;
        k_zstats<<<dim3(FIN, BATCH), 256>>>(cur, Zh, meanb, rstdb);
        k_fold<<<dim3(64, BATCH), FIN>>>(Pc, meanb, rstdb, AT, bfold);
        k_g1_mma<<<dim3(HW / 128, BATCH), 256>>>(AT, Zh, bfold, HS);
        k_g2<<<dim3(HW / 128, BATCH), dim3(32, 8)>>>(Pc, HS, nxt);
        k_freq<<<dim3(NF, BATCH), 256>>>(nxt, pe, freqb);
        k_cat_h2<<<dim3(16, 8), 128>>>(lcur, freqb, otl_w1 + (size_t)c * CAT * CAT, t1part);
        k_cat_o2<<<dim3(4, 8), 128>>>(lcur, freqb, t1part, otl_b1 + c * CAT,
                                      otl_w2 + (size_t)c * CAT * LAT, otl_b2 + c * LAT,
                                      otl_ws + (size_t)c * CAT * LAT, otl_bs + c * LAT,
                                      latpart);
        k_fin8<<<BATCH * LAT / 256, 256>>>(latpart, lnxt, BATCH * LAT);
        { float* t = cur; cur = nxt; nxt = t; }
        { float* t = lcur; lcur = lnxt; lnxt = t; }
    }
    k_final<<<dim3(4, 4), 128>>>(lcur, ltl_w, ltl_b, (float*)d_out);
}

// round 5
// speedup vs baseline: 3.1686x; 1.4917x over previous
#include <cuda_runtime.h>
#include <cuda_fp16.h>
#include <cuda_bf16.h>
#include <math.h>

// ---------------- constants ----------------
#define BATCH 16
#define NF 64
#define LAT 512
#define IMGD 64
#define HW 4096          // 64*64
#define NC 4
#define CF 9
#define FIN 576          // NF*CF
#define NFREQ 6
#define FCH 24           // 4*NFREQ
#define FREQN 1536       // NF*FCH
#define CAT 2048         // LAT + NF*FCH
#define P_DYN 78016
// P layout offsets
#define OFF_KIN 0        // [64][576]
#define OFF_BIN 36864    // [64]
#define OFF_KOUT 36928   // [64][64]
#define OFF_BOUT 41024   // [64]
#define OFF_KSK 41088    // [64][576]
#define OFF_BSK 77952    // [64]

// fused g1g2 dynamic smem: As[2][16][136] + Bs[2][16][136] + hS[64][136] + koT[64][72]
#define SM_AS 0
#define SM_BS (2 * 16 * 136)
#define SM_HS (4 * 16 * 136)
#define SM_KO (4 * 16 * 136 + 64 * 136)
#define SM_TOTAL_U32 (4 * 16 * 136 + 64 * 136 + 64 * 72)
#define SMEM_G1G2_BYTES (SM_TOTAL_U32 * 4)

// ---------------- scratch (device globals; no allocation) ----------------
__device__ float g_chain[4 * BATCH * LAT];
__device__ float g_hpart[8 * BATCH * LAT];
__device__ float g_opart[8 * BATCH * LAT];
__device__ float g_t1part[8 * BATCH * CAT];
__device__ float g_latpart[8 * BATCH * LAT];
__device__ float g_P[64ull * P_DYN];
__device__ float g_img0[BATCH * NF * HW];
__device__ float g_img1[BATCH * NF * HW];
__device__ __half g_Zh[(size_t)BATCH * FIN * HW];
__device__ float g_AT[BATCH * FIN * 128];
__device__ float g_bfold[BATCH * 128];
__device__ float g_mean[BATCH * FIN];
__device__ float g_rstd[BATCH * FIN];
__device__ float g_freq[BATCH * FREQN];
__device__ float g_latA[BATCH * LAT];
__device__ float g_latB[BATCH * LAT];

__device__ __forceinline__ float leaky(float v) { return v > 0.f ? v : 0.2f * v; }

__device__ __forceinline__ unsigned f2tf(float v) {
    unsigned r;
    asm("cvt.rna.tf32.f32 %0, %1;" : "=r"(r) : "f"(v));
    return r;
}

__device__ __forceinline__ uint4 h4_to_tf(uint2 v) {
    __half2 a = *(__half2*)&v.x, b = *(__half2*)&v.y;
    float2 fa = __half22float2(a), fb = __half22float2(b);
    return make_uint4(f2tf(fa.x), f2tf(fa.y), f2tf(fb.x), f2tf(fb.y));
}

// ---------------- input image projection ----------------
__global__ void k_inimg(const float* __restrict__ x, const float* __restrict__ w_in,
                        const float* __restrict__ b_in, float* __restrict__ img) {
    int idx = blockIdx.x * 256 + threadIdx.x;
    if (idx >= BATCH * NF * HW) return;
    int p = idx & (HW - 1);
    int o = (idx >> 12) & 63;
    int b = idx >> 18;
    const float* xb = x + (size_t)b * 3 * HW;
    float v = b_in[o] + w_in[o * 3 + 0] * xb[p] + w_in[o * 3 + 1] * xb[HW + p]
            + w_in[o * 3 + 2] * xb[2 * HW + p];
    img[idx] = v;
}

// ---------------- generic 8-way partial reduce ----------------
__global__ void k_fin8(const float* __restrict__ part, float* __restrict__ out, int n) {
    int i = blockIdx.x * 256 + threadIdx.x;
    if (i >= n) return;
    float s = 0.f;
#pragma unroll
    for (int p = 0; p < 8; p++) s += part[p * n + i];
    out[i] = s;
}

// ---------------- lin_res 512 phase 1 (split-k partials of x@w1) ----------------
__global__ __launch_bounds__(128) void k_lin_h2(const float* __restrict__ in,
                                                const float* __restrict__ w1,
                                                float* __restrict__ hpart) {
    __shared__ float xs[16][64];
    int j = blockIdx.x * 128 + threadIdx.x;
    int k0 = blockIdx.y * 64;
    for (int t = threadIdx.x; t < 16 * 64; t += 128)
        xs[t >> 6][t & 63] = in[(t >> 6) * LAT + k0 + (t & 63)];
    __syncthreads();
    float acc[16];
#pragma unroll
    for (int bb = 0; bb < 16; bb++) acc[bb] = 0.f;
#pragma unroll 4
    for (int kk = 0; kk < 64; kk++) {
        float w = w1[(size_t)(k0 + kk) * LAT + j];
#pragma unroll
        for (int bb = 0; bb < 16; bb++) acc[bb] += xs[bb][kk] * w;
    }
#pragma unroll
    for (int bb = 0; bb < 16; bb++)
        hpart[(blockIdx.y * 16 + bb) * LAT + j] = acc[bb];
}

// ---------------- lin_res 512 phase 2 (x@ws + h@w2, h reduced inline) ----------------
__global__ __launch_bounds__(128) void k_lin_o2(const float* __restrict__ in,
                                                const float* __restrict__ hpart,
                                                const float* __restrict__ b1,
                                                const float* __restrict__ ws,
                                                const float* __restrict__ w2,
                                                const float* __restrict__ bs,
                                                const float* __restrict__ b2,
                                                float* __restrict__ opart) {
    __shared__ float xs[16][64];
    __shared__ float hs[16][64];
    int j = blockIdx.x * 128 + threadIdx.x;
    int k0 = blockIdx.y * 64;
    for (int t = threadIdx.x; t < 16 * 64; t += 128) {
        int bb = t >> 6, kk = t & 63;
        int k = k0 + kk;
        xs[bb][kk] = in[bb * LAT + k];
        float s = b1[k];
#pragma unroll
        for (int p = 0; p < 8; p++) s += hpart[(p * 16 + bb) * LAT + k];
        hs[bb][kk] = leaky(s);
    }
    __syncthreads();
    float acc[16];
#pragma unroll
    for (int bb = 0; bb < 16; bb++) acc[bb] = 0.f;
#pragma unroll 4
    for (int kk = 0; kk < 64; kk++) {
        float a = ws[(size_t)(k0 + kk) * LAT + j];
        float c = w2[(size_t)(k0 + kk) * LAT + j];
#pragma unroll
        for (int bb = 0; bb < 16; bb++) acc[bb] += xs[bb][kk] * a + hs[bb][kk] * c;
    }
    float bias = (blockIdx.y == 0) ? (bs[j] + b2[j]) : 0.f;
#pragma unroll
    for (int bb = 0; bb < 16; bb++)
        opart[(blockIdx.y * 16 + bb) * LAT + j] = acc[bb] + bias;
}

// ---------------- dyn params GEMM: [64,512] @ [512,78016] + bias ----------------
__global__ __launch_bounds__(256) void k_dyngemm(const float* __restrict__ lat,
                                                 const float* __restrict__ W,
                                                 const float* __restrict__ bias,
                                                 float* __restrict__ P) {
    __shared__ float ls[32][65];
    int tid = threadIdx.y * 32 + threadIdx.x;
    int col0 = blockIdx.x * 128 + threadIdx.x * 4;
    bool ok = col0 < P_DYN;
    float acc[8][4];
#pragma unroll
    for (int r = 0; r < 8; r++)
#pragma unroll
        for (int c = 0; c < 4; c++) acc[r][c] = 0.f;

    for (int k0 = 0; k0 < LAT; k0 += 32) {
#pragma unroll
        for (int t = 0; t < 8; t++) {
            int idx = tid + t * 256;
            int m = idx >> 5, kk = idx & 31;
            ls[kk][m] = lat[m * LAT + k0 + kk];
        }
        __syncthreads();
        if (ok) {
#pragma unroll
            for (int kk = 0; kk < 32; kk++) {
                float4 w = *(const float4*)(W + (size_t)(k0 + kk) * P_DYN + col0);
#pragma unroll
                for (int r = 0; r < 8; r++) {
                    float l = ls[kk][threadIdx.y * 8 + r];
                    acc[r][0] += l * w.x; acc[r][1] += l * w.y;
                    acc[r][2] += l * w.z; acc[r][3] += l * w.w;
                }
            }
        }
        __syncthreads();
    }
    if (ok) {
        float4 bv = *(const float4*)(bias + col0);
#pragma unroll
        for (int r = 0; r < 8; r++) {
            int m = threadIdx.y * 8 + r;
            float4 o;
            o.x = acc[r][0] + bv.x; o.y = acc[r][1] + bv.y;
            o.z = acc[r][2] + bv.z; o.w = acc[r][3] + bv.w;
            *(float4*)(P + (size_t)m * P_DYN + col0) = o;
        }
    }
}

// ---------------- perceive + stats (Z (fp16) materialize + mean/rstd, fp32 stats) ----------------
__global__ void k_zstats(const float* __restrict__ img, __half* __restrict__ Z,
                         float* __restrict__ mean, float* __restrict__ rstd) {
    int b = blockIdx.y;
    int i = blockIdx.x;                 // 0..575
    int g = i >> 6, f = i & 63;
    const float* O = img + (size_t)(b * NF + f) * HW;
    __half* zrow = Z + ((size_t)b * FIN + i) * HW;
    float s1 = 0.f, s2 = 0.f;

    if (g == 0) {
        for (int p = threadIdx.x; p < HW; p += 256) {
            float v = O[p];
            zrow[p] = __float2half(v); s1 += v; s2 += v * v;
        }
    } else {
        int d = 1 << ((g - 1) >> 1);
        bool isSX = ((g - 1) & 1) == 0;
        for (int p = threadIdx.x; p < HW; p += 256) {
            int h = p >> 6, w = p & 63;
            int hm = h - d, hp = h + d, wm = w - d, wp = w + d;
            bool hmv = hm >= 0, hpv = hp < IMGD, wmv = wm >= 0, wpv = wp < IMGD;
            float v;
            if (isSX) {
                float t = 0.f;
                if (wmv) {
                    if (hmv) t -= O[hm * IMGD + wm];
                    t -= 2.f * O[h * IMGD + wm];
                    if (hpv) t -= O[hp * IMGD + wm];
                }
                if (wpv) {
                    if (hmv) t += O[hm * IMGD + wp];
                    t += 2.f * O[h * IMGD + wp];
                    if (hpv) t += O[hp * IMGD + wp];
                }
                v = 0.125f * t;
            } else {
                float t = 0.f;
                if (hmv) {
                    if (wmv) t -= O[hm * IMGD + wm];
                    t -= 2.f * O[hm * IMGD + w];
                    if (wpv) t -= O[hm * IMGD + wp];
                }
                if (hpv) {
                    if (wmv) t += O[hp * IMGD + wm];
                    t += 2.f * O[hp * IMGD + w];
                    if (wpv) t += O[hp * IMGD + wp];
                }
                v = 0.125f * t;
            }
            zrow[p] = __float2half(v); s1 += v; s2 += v * v;
        }
    }
    __shared__ float rs1[8], rs2[8];
    int lane = threadIdx.x & 31, wid = threadIdx.x >> 5;
#pragma unroll
    for (int off = 16; off; off >>= 1) {
        s1 += __shfl_down_sync(0xffffffffu, s1, off);
        s2 += __shfl_down_sync(0xffffffffu, s2, off);
    }
    if (lane == 0) { rs1[wid] = s1; rs2[wid] = s2; }
    __syncthreads();
    if (threadIdx.x == 0) {
        float t1 = 0.f, t2 = 0.f;
        for (int w = 0; w < 8; w++) { t1 += rs1[w]; t2 += rs2[w]; }
        float m = t1 * (1.0f / 4096.0f);
        float var = t2 * (1.0f / 4096.0f) - m * m;
        mean[b * FIN + i] = m;
        rstd[b * FIN + i] = 1.0f / sqrtf(var + 1e-5f);
    }
}

// ---------------- fold inorm into dynamic weights ----------------
__global__ void k_fold(const float* __restrict__ P, const float* __restrict__ mean,
                       const float* __restrict__ rstd, float* __restrict__ AT,
                       float* __restrict__ bfold) {
    int b = blockIdx.y, f = blockIdx.x;
    const float* pb = P + (size_t)b * P_DYN;
    int i = threadIdx.x;  // 0..575
    float r = rstd[b * FIN + i], m = mean[b * FIN + i];
    float win = pb[OFF_KIN + f * FIN + i] * r;
    float wsk = pb[OFF_KSK + f * FIN + i] * r;
    AT[(size_t)b * FIN * 128 + i * 128 + f] = win;
    AT[(size_t)b * FIN * 128 + i * 128 + 64 + f] = wsk;
    float t1 = win * m, t2 = wsk * m;
    __shared__ float r1[18], r2[18];
    int lane = threadIdx.x & 31, wid = threadIdx.x >> 5;
#pragma unroll
    for (int off = 16; off; off >>= 1) {
        t1 += __shfl_down_sync(0xffffffffu, t1, off);
        t2 += __shfl_down_sync(0xffffffffu, t2, off);
    }
    if (lane == 0) { r1[wid] = t1; r2[wid] = t2; }
    __syncthreads();
    if (threadIdx.x == 0) {
        float s1 = 0.f, s2 = 0.f;
        for (int w = 0; w < 18; w++) { s1 += r1[w]; s2 += r2[w]; }
        bfold[b * 128 + f] = pb[OFF_BIN + f] - s1;
        bfold[b * 128 + 64 + f] = pb[OFF_BSK + f] - s2;
    }
}

// ---------------- FUSED dyna-conv: [128,576]@[576,4096] + k_out@leaky + skip ----------------
// grid (32 px-tiles, 16 batch), block 256 (8 warps: 2 ch-halves x 4 px-quarters)
// stage 1: H/S = ATw @ Z (tf32 mma); stage 2 (skip warps): out = koT @ leaky(H) + S + b_out
__global__ __launch_bounds__(256) void k_g1g2(const float* __restrict__ AT,
                                              const __half* __restrict__ Z,
                                              const float* __restrict__ bfold,
                                              const float* __restrict__ P,
                                              float* __restrict__ outimg) {
    extern __shared__ unsigned smemRaw[];
    unsigned (*As)[16][136] = (unsigned(*)[16][136])(smemRaw + SM_AS);
    unsigned (*Bs)[16][136] = (unsigned(*)[16][136])(smemRaw + SM_BS);
    unsigned (*hS)[136]     = (unsigned(*)[136])(smemRaw + SM_HS);
    unsigned (*koT)[72]     = (unsigned(*)[72])(smemRaw + SM_KO);

    int b = blockIdx.y;
    int p0 = blockIdx.x * 128;
    const float* At = AT + (size_t)b * FIN * 128;
    const __half* Zb = Z + (size_t)b * FIN * HW;
    const float* pb = P + (size_t)b * P_DYN;
    int tid = threadIdx.x, lane = tid & 31, warp = tid >> 5;
    int ch0 = (warp & 1) * 64;
    int px0 = (warp >> 1) * 32;
    int r = lane >> 2, cc = lane & 3;

    // stage-2 A operand: koT[f][o] = ko[o][f], tf32
    for (int idx = tid; idx < 4096; idx += 256) {
        int o = idx >> 6, f = idx & 63;
        koT[f][o] = f2tf(pb[OFF_KOUT + idx]);
    }

    float acc[4][4][4];
#pragma unroll
    for (int mt = 0; mt < 4; mt++)
#pragma unroll
        for (int nt = 0; nt < 4; nt++)
#pragma unroll
            for (int q = 0; q < 4; q++) acc[mt][nt][q] = 0.f;

    int rowL = tid >> 5;        // 0..7
    int colL = lane * 4;        // 0..124

    // stage chunk 0
    float4 va0 = *(const float4*)(At + (size_t)rowL * 128 + colL);
    float4 va1 = *(const float4*)(At + (size_t)(rowL + 8) * 128 + colL);
    uint2 vb0 = *(const uint2*)(Zb + (size_t)rowL * HW + p0 + colL);
    uint2 vb1 = *(const uint2*)(Zb + (size_t)(rowL + 8) * HW + p0 + colL);
    *(uint4*)&As[0][rowL][colL]     = make_uint4(f2tf(va0.x), f2tf(va0.y), f2tf(va0.z), f2tf(va0.w));
    *(uint4*)&As[0][rowL + 8][colL] = make_uint4(f2tf(va1.x), f2tf(va1.y), f2tf(va1.z), f2tf(va1.w));
    *(uint4*)&Bs[0][rowL][colL]     = h4_to_tf(vb0);
    *(uint4*)&Bs[0][rowL + 8][colL] = h4_to_tf(vb1);
    __syncthreads();

    for (int t = 0; t < 36; t++) {
        int cur = t & 1;
        float4 na0, na1;
        uint2 nb0, nb1;
        if (t < 35) {
            int i0 = (t + 1) * 16;
            na0 = *(const float4*)(At + (size_t)(i0 + rowL) * 128 + colL);
            na1 = *(const float4*)(At + (size_t)(i0 + rowL + 8) * 128 + colL);
            nb0 = *(const uint2*)(Zb + (size_t)(i0 + rowL) * HW + p0 + colL);
            nb1 = *(const uint2*)(Zb + (size_t)(i0 + rowL + 8) * HW + p0 + colL);
        }
#pragma unroll
        for (int ks = 0; ks < 2; ks++) {
            int kk = ks * 8;
            unsigned af[4][4], bf[4][2];
#pragma unroll
            for (int mt = 0; mt < 4; mt++) {
                int m = ch0 + mt * 16;
                af[mt][0] = As[cur][kk + cc][m + r];
                af[mt][1] = As[cur][kk + cc][m + r + 8];
                af[mt][2] = As[cur][kk + cc + 4][m + r];
                af[mt][3] = As[cur][kk + cc + 4][m + r + 8];
            }
#pragma unroll
            for (int nt = 0; nt < 4; nt++) {
                int n = px0 + nt * 8 + r;
                bf[nt][0] = Bs[cur][kk + cc][n];
                bf[nt][1] = Bs[cur][kk + cc + 4][n];
            }
#pragma unroll
            for (int mt = 0; mt < 4; mt++)
#pragma unroll
                for (int nt = 0; nt < 4; nt++) {
                    asm volatile(
                        "mma.sync.aligned.m16n8k8.row.col.f32.tf32.tf32.f32 "
                        "{%0,%1,%2,%3}, {%4,%5,%6,%7}, {%8,%9}, {%0,%1,%2,%3};"
                        : "+f"(acc[mt][nt][0]), "+f"(acc[mt][nt][1]),
                          "+f"(acc[mt][nt][2]), "+f"(acc[mt][nt][3])
                        : "r"(af[mt][0]), "r"(af[mt][1]), "r"(af[mt][2]), "r"(af[mt][3]),
                          "r"(bf[nt][0]), "r"(bf[nt][1]));
                }
        }
        if (t < 35) {
            int nxt = cur ^ 1;
            *(uint4*)&As[nxt][rowL][colL]     = make_uint4(f2tf(na0.x), f2tf(na0.y), f2tf(na0.z), f2tf(na0.w));
            *(uint4*)&As[nxt][rowL + 8][colL] = make_uint4(f2tf(na1.x), f2tf(na1.y), f2tf(na1.z), f2tf(na1.w));
            *(uint4*)&Bs[nxt][rowL][colL]     = h4_to_tf(nb0);
            *(uint4*)&Bs[nxt][rowL + 8][colL] = h4_to_tf(nb1);
        }
        __syncthreads();
    }

    // stage-1 epilogue
    if (ch0 == 0) {
        // h warps: bias + leaky -> hS (tf32), layout [f 0..63][px 0..127]
#pragma unroll
        for (int mt = 0; mt < 4; mt++) {
            int row0 = mt * 16 + r;
            int row1 = row0 + 8;
            float bi0 = bfold[b * 128 + row0];
            float bi1 = bfold[b * 128 + row1];
#pragma unroll
            for (int nt = 0; nt < 4; nt++) {
                int col = px0 + nt * 8 + 2 * cc;
                hS[row0][col]     = f2tf(leaky(acc[mt][nt][0] + bi0));
                hS[row0][col + 1] = f2tf(leaky(acc[mt][nt][1] + bi0));
                hS[row1][col]     = f2tf(leaky(acc[mt][nt][2] + bi1));
                hS[row1][col + 1] = f2tf(leaky(acc[mt][nt][3] + bi1));
            }
        }
    } else {
        // skip warps: add folded skip bias into accumulators
#pragma unroll
        for (int mt = 0; mt < 4; mt++) {
            float bi0 = bfold[b * 128 + 64 + mt * 16 + r];
            float bi1 = bfold[b * 128 + 64 + mt * 16 + r + 8];
#pragma unroll
            for (int nt = 0; nt < 4; nt++) {
                acc[mt][nt][0] += bi0; acc[mt][nt][1] += bi0;
                acc[mt][nt][2] += bi1; acc[mt][nt][3] += bi1;
            }
        }
    }
    __syncthreads();

    // stage 2: out = koT @ h + skip (skip warps only; K = 64)
    if (ch0 == 64) {
#pragma unroll
        for (int kc = 0; kc < 8; kc++) {
            int kk = kc * 8;
            unsigned af[4][4], bf[4][2];
#pragma unroll
            for (int mt = 0; mt < 4; mt++) {
                int m = mt * 16;
                af[mt][0] = koT[kk + cc][m + r];
                af[mt][1] = koT[kk + cc][m + r + 8];
                af[mt][2] = koT[kk + cc + 4][m + r];
                af[mt][3] = koT[kk + cc + 4][m + r + 8];
            }
#pragma unroll
            for (int nt = 0; nt < 4; nt++) {
                int n = px0 + nt * 8 + r;
                bf[nt][0] = hS[kk + cc][n];
                bf[nt][1] = hS[kk + cc + 4][n];
            }
#pragma unroll
            for (int mt = 0; mt < 4; mt++)
#pragma unroll
                for (int nt = 0; nt < 4; nt++) {
                    asm volatile(
                        "mma.sync.aligned.m16n8k8.row.col.f32.tf32.tf32.f32 "
                        "{%0,%1,%2,%3}, {%4,%5,%6,%7}, {%8,%9}, {%0,%1,%2,%3};"
                        : "+f"(acc[mt][nt][0]), "+f"(acc[mt][nt][1]),
                          "+f"(acc[mt][nt][2]), "+f"(acc[mt][nt][3])
                        : "r"(af[mt][0]), "r"(af[mt][1]), "r"(af[mt][2]), "r"(af[mt][3]),
                          "r"(bf[nt][0]), "r"(bf[nt][1]));
                }
        }
        // final epilogue: + b_out, write output image
#pragma unroll
        for (int mt = 0; mt < 4; mt++) {
            int o0 = mt * 16 + r;
            int o1 = o0 + 8;
            float bo0 = pb[OFF_BOUT + o0];
            float bo1 = pb[OFF_BOUT + o1];
#pragma unroll
            for (int nt = 0; nt < 4; nt++) {
                int gcol = p0 + px0 + nt * 8 + 2 * cc;
                *(float2*)(outimg + ((size_t)b * NF + o0) * HW + gcol) =
                    make_float2(acc[mt][nt][0] + bo0, acc[mt][nt][1] + bo0);
                *(float2*)(outimg + ((size_t)b * NF + o1) * HW + gcol) =
                    make_float2(acc[mt][nt][2] + bo1, acc[mt][nt][3] + bo1);
            }
        }
    }
}

// ---------------- frequency readout ----------------
__global__ void k_freq(const float* __restrict__ img, const float* __restrict__ pe,
                       float* __restrict__ freqout) {
    int b = blockIdx.y, ch = blockIdx.x;
    const float* O = img + (size_t)(b * NF + ch) * HW;
    float acc[FCH];
#pragma unroll
    for (int f = 0; f < FCH; f++) acc[f] = 0.f;
    for (int p = threadIdx.x; p < HW; p += 256) {
        float v = O[p];
#pragma unroll
        for (int f = 0; f < FCH; f++) acc[f] += v * pe[f * HW + p];
    }
    __shared__ float red[FCH][9];
    int lane = threadIdx.x & 31, wid = threadIdx.x >> 5;
#pragma unroll
    for (int f = 0; f < FCH; f++) {
        float v = acc[f];
#pragma unroll
        for (int off = 16; off; off >>= 1) v += __shfl_down_sync(0xffffffffu, v, off);
        if (lane == 0) red[f][wid] = v;
    }
    __syncthreads();
    if (threadIdx.x < FCH) {
        float s = 0.f;
        for (int w = 0; w < 8; w++) s += red[threadIdx.x][w];
        freqout[b * FREQN + ch * FCH + threadIdx.x] = s * (1.0f / 4096.0f);
    }
}

// ---------------- otl phase A: split-k partials of cat @ w1 ----------------
__global__ __launch_bounds__(128) void k_cat_h2(const float* __restrict__ latfin,
                                                const float* __restrict__ freq,
                                                const float* __restrict__ w1,
                                                float* __restrict__ t1part) {
    __shared__ float cs[16][256];
    int j = blockIdx.x * 128 + threadIdx.x;
    int k0 = blockIdx.y * 256;
    for (int t = threadIdx.x; t < 16 * 256; t += 128) {
        int bb = t >> 8, kk = t & 255;
        int k = k0 + kk;
        cs[bb][kk] = (k < LAT) ? latfin[bb * LAT + k] : freq[bb * FREQN + k - LAT];
    }
    __syncthreads();
    float acc[16];
#pragma unroll
    for (int bb = 0; bb < 16; bb++) acc[bb] = 0.f;
#pragma unroll 4
    for (int kk = 0; kk < 256; kk++) {
        float w = w1[(size_t)(k0 + kk) * CAT + j];
#pragma unroll
        for (int bb = 0; bb < 16; bb++) acc[bb] += cs[bb][kk] * w;
    }
#pragma unroll
    for (int bb = 0; bb < 16; bb++)
        t1part[(blockIdx.y * 16 + bb) * CAT + j] = acc[bb];
}

// ---------------- otl phase B: cat@ws + t1@w2 (t1 reduced+leaky inline) ----------------
__global__ __launch_bounds__(128) void k_cat_o2(const float* __restrict__ latfin,
                                                const float* __restrict__ freq,
                                                const float* __restrict__ t1part,
                                                const float* __restrict__ b1,
                                                const float* __restrict__ w2,
                                                const float* __restrict__ b2,
                                                const float* __restrict__ ws,
                                                const float* __restrict__ bs,
                                                float* __restrict__ latpart) {
    __shared__ float cs[16][256];
    __shared__ float ts[16][256];
    int j = blockIdx.x * 128 + threadIdx.x;
    int k0 = blockIdx.y * 256;
    for (int t = threadIdx.x; t < 16 * 256; t += 128) {
        int bb = t >> 8, kk = t & 255;
        int k = k0 + kk;
        cs[bb][kk] = (k < LAT) ? latfin[bb * LAT + k] : freq[bb * FREQN + k - LAT];
        float s = b1[k];
#pragma unroll
        for (int p = 0; p < 8; p++) s += t1part[(p * 16 + bb) * CAT + k];
        ts[bb][kk] = leaky(s);
    }
    __syncthreads();
    float acc[16];
#pragma unroll
    for (int bb = 0; bb < 16; bb++) acc[bb] = 0.f;
#pragma unroll 4
    for (int kk = 0; kk < 256; kk++) {
        float a = ws[(size_t)(k0 + kk) * LAT + j];
        float c = w2[(size_t)(k0 + kk) * LAT + j];
#pragma unroll
        for (int bb = 0; bb < 16; bb++) acc[bb] += cs[bb][kk] * a + ts[bb][kk] * c;
    }
    float bias = (blockIdx.y == 0) ? (bs[j] + b2[j]) : 0.f;
#pragma unroll
    for (int bb = 0; bb < 16; bb++)
        latpart[(blockIdx.y * 16 + bb) * LAT + j] = acc[bb] + bias;
}

// ---------------- final projection ----------------
__global__ __launch_bounds__(128) void k_final(const float* __restrict__ lat,
                                               const float* __restrict__ w,
                                               const float* __restrict__ bb,
                                               float* __restrict__ out) {
    __shared__ float xs[4][LAT];
    int j = blockIdx.x * 128 + threadIdx.x;
    int bb0 = blockIdx.y * 4;
    for (int t = threadIdx.x; t < 4 * LAT; t += 128)
        xs[t >> 9][t & 511] = lat[(bb0 + (t >> 9)) * LAT + (t & 511)];
    __syncthreads();
    float a0 = 0.f, a1 = 0.f, a2 = 0.f, a3 = 0.f;
#pragma unroll 8
    for (int k = 0; k < LAT; k++) {
        float wv = w[(size_t)k * LAT + j];
        a0 += xs[0][k] * wv; a1 += xs[1][k] * wv;
        a2 += xs[2][k] * wv; a3 += xs[3][k] * wv;
    }
    float bv = bb[j];
    out[(bb0 + 0) * LAT + j] = a0 + bv;
    out[(bb0 + 1) * LAT + j] = a1 + bv;
    out[(bb0 + 2) * LAT + j] = a2 + bv;
    out[(bb0 + 3) * LAT + j] = a3 + bv;
}

// ---------------- launch ----------------
extern "C" void kernel_launch(void* const* d_in, const int* in_sizes, int n_in,
                              void* d_out, int out_size) {
    const float* x       = (const float*)d_in[0];
    const float* inj_lat = (const float*)d_in[1];
    const float* w_in    = (const float*)d_in[2];
    const float* b_in    = (const float*)d_in[3];
    const float* fl_w1   = (const float*)d_in[4];
    const float* fl_b1   = (const float*)d_in[5];
    const float* fl_w2   = (const float*)d_in[6];
    const float* fl_b2   = (const float*)d_in[7];
    const float* fl_ws   = (const float*)d_in[8];
    const float* fl_bs   = (const float*)d_in[9];
    const float* dyn_w   = (const float*)d_in[10];
    const float* dyn_b   = (const float*)d_in[11];
    const float* pe      = (const float*)d_in[12];
    const float* otl_w1  = (const float*)d_in[13];
    const float* otl_b1  = (const float*)d_in[14];
    const float* otl_w2  = (const float*)d_in[15];
    const float* otl_b2  = (const float*)d_in[16];
    const float* otl_ws  = (const float*)d_in[17];
    const float* otl_bs  = (const float*)d_in[18];
    const float* ltl_w   = (const float*)d_in[19];
    const float* ltl_b   = (const float*)d_in[20];

    float *chain, *hpart, *opart, *t1part, *latpart, *P, *img0, *img1, *AT, *bfold,
          *meanb, *rstdb, *freqb, *latA, *latB;
    __half* Zh;
    cudaGetSymbolAddress((void**)&chain, g_chain);
    cudaGetSymbolAddress((void**)&hpart, g_hpart);
    cudaGetSymbolAddress((void**)&opart, g_opart);
    cudaGetSymbolAddress((void**)&t1part, g_t1part);
    cudaGetSymbolAddress((void**)&latpart, g_latpart);
    cudaGetSymbolAddress((void**)&P, g_P);
    cudaGetSymbolAddress((void**)&img0, g_img0);
    cudaGetSymbolAddress((void**)&img1, g_img1);
    cudaGetSymbolAddress((void**)&Zh, g_Zh);
    cudaGetSymbolAddress((void**)&AT, g_AT);
    cudaGetSymbolAddress((void**)&bfold, g_bfold);
    cudaGetSymbolAddress((void**)&meanb, g_mean);
    cudaGetSymbolAddress((void**)&rstdb, g_rstd);
    cudaGetSymbolAddress((void**)&freqb, g_freq);
    cudaGetSymbolAddress((void**)&latA, g_latA);
    cudaGetSymbolAddress((void**)&latB, g_latB);

    cudaFuncSetAttribute(k_g1g2, cudaFuncAttributeMaxDynamicSharedMemorySize,
                         SMEM_G1G2_BYTES);

    cudaMemsetAsync(latA, 0, BATCH * LAT * sizeof(float));

    k_inimg<<<(BATCH * NF * HW + 255) / 256, 256>>>(x, w_in, b_in, img0);

    // latent chain (image-independent), split-k
    {
        const float* cin = inj_lat;
        for (int t = 0; t < 4; t++) {
            float* cout = chain + t * BATCH * LAT;
            k_lin_h2<<<dim3(4, 8), 128>>>(cin, fl_w1, hpart);
            k_lin_o2<<<dim3(4, 8), 128>>>(cin, hpart, fl_b1, fl_ws, fl_w2, fl_bs, fl_b2, opart);
            k_fin8<<<BATCH * LAT / 256, 256>>>(opart, cout, BATCH * LAT);
            cin = cout;
        }
    }

    // all 4 iterations' dynamic params in ONE pass over dyn_w
    k_dyngemm<<<(P_DYN + 127) / 128, dim3(32, 8)>>>(chain, dyn_w, dyn_b, P);

    float* cur = img0; float* nxt = img1;
    float* lcur = latA; float* lnxt = latB;
    for (int c = 0; c < NC; c++) {
        const float* Pc = P + (size_t)c * BATCH * P_DYN;
        k_zstats<<<dim3(FIN, BATCH), 256>>>(cur, Zh, meanb, rstdb);
        k_fold<<<dim3(64, BATCH), FIN>>>(Pc, meanb, rstdb, AT, bfold);
        k_g1g2<<<dim3(HW / 128, BATCH), 256, SMEM_G1G2_BYTES>>>(AT, Zh, bfold, Pc, nxt);
        k_freq<<<dim3(NF, BATCH), 256>>>(nxt, pe, freqb);
        k_cat_h2<<<dim3(16, 8), 128>>>(lcur, freqb, otl_w1 + (size_t)c * CAT * CAT, t1part);
        k_cat_o2<<<dim3(4, 8), 128>>>(lcur, freqb, t1part, otl_b1 + c * CAT,
                                      otl_w2 + (size_t)c * CAT * LAT, otl_b2 + c * LAT,
                                      otl_ws + (size_t)c * CAT * LAT, otl_bs + c * LAT,
                                      latpart);
        k_fin8<<<BATCH * LAT / 256, 256>>>(latpart, lnxt, BATCH * LAT);
        { float* t = cur; cur = nxt; nxt = t; }
        { float* t = lcur; lcur = lnxt; lnxt = t; }
    }
    k_final<<<dim3(4, 4), 128>>>(lcur, ltl_w, ltl_b, (float*)d_out);
}